// round 8
// baseline (speedup 1.0000x reference)
#include <cuda_runtime.h>
#include <cuda_fp16.h>
#include <math.h>

#define NA   4096
#define FDIM 128
#define NH   4
#define DH   32
#define KNN  15
#define NKR  50
#define NL   6
#define NEDGE (NA*KNN)
#define WT   16            // RBF window taps

// ekv kernel tiling: block = 128 edges x 256 cols, warp = 4-edge group
#define EKV_EB    128
#define EKV_NPASS 4
#define RPAD      50
#define ECOL      256      // live output cols: [ek(128) | ev1(128)]

// ---------------- scratch (static device globals; no runtime alloc) --------
// The reference's vector channel v (m2/m3/vec_norm) never reaches the output
// (o only accumulates ds) — dead code, not computed.
__device__ float  d_s[NA*FDIM];
__device__ float  d_o[NA*FDIM];
__device__ float  d_q[NA*FDIM];            // fp32 q (self-read only)
__device__ __half d_kvh[NA*256];           // fp16 [k(128) | val1(128)] (gathered)
__device__ __half d_ekvh[NL][NEDGE*ECOL];  // fp16 [ek(128)|ev1(128)] per layer
__device__ float  d_cut[NEDGE];
__device__ float  d_dist[NEDGE];
__device__ int    d_idx[NEDGE];
__device__ float  d_h[NA];

// ---------------- init ------------------------------------------------------
__global__ void init_kernel(const int* __restrict__ Z, const float* __restrict__ emb) {
    int t = blockIdx.x * blockDim.x + threadIdx.x;
    if (t < NA*FDIM) {
        int i = t / FDIM, f = t % FDIM;
        d_s[t] = emb[Z[i]*FDIM + f];
        d_o[t] = 0.f;
    }
}

// ---------------- KNN + edge geometry (shfl-based argmin) -------------------
__global__ void knn_kernel(const float* __restrict__ R) {
    __shared__ float sd2[NA];
    __shared__ float swv[8];
    __shared__ int   swj[8];
    __shared__ int   sidx[KNN];

    int i = blockIdx.x, t = threadIdx.x;
    int lane = t & 31, wrp = t >> 5;
    float rx = R[i*3], ry = R[i*3+1], rz = R[i*3+2];
    float sqi = rx*rx + ry*ry + rz*rz;

    for (int j = t; j < NA; j += 256) {
        float x = R[j*3], y = R[j*3+1], z = R[j*3+2];
        float sqj = x*x + y*y + z*z;
        float dot = rx*x + ry*y + rz*z;
        float d2  = fmaxf(sqi + sqj - 2.f*dot, 0.f);
        if (j == i) d2 = 1e9f;
        sd2[j] = d2;
    }
    __syncthreads();

    for (int k = 0; k < KNN; k++) {
        float bv = 1e30f; int bj = 0x7fffffff;
        #pragma unroll
        for (int u = 0; u < NA/256; u++) {
            int j = t + u*256;
            float v = sd2[j];
            if (v < bv) { bv = v; bj = j; }     // strict < keeps lowest index
        }
        // warp argmin (value, lowest index on tie)
        #pragma unroll
        for (int off = 16; off; off >>= 1) {
            float v2 = __shfl_down_sync(0xffffffffu, bv, off);
            int   j2 = __shfl_down_sync(0xffffffffu, bj, off);
            if (v2 < bv || (v2 == bv && j2 < bj)) { bv = v2; bj = j2; }
        }
        if (lane == 0) { swv[wrp] = bv; swj[wrp] = bj; }
        __syncthreads();
        if (t == 0) {
            float fv = swv[0]; int fj = swj[0];
            #pragma unroll
            for (int wdx = 1; wdx < 8; wdx++) {
                float v2 = swv[wdx]; int j2 = swj[wdx];
                if (v2 < fv || (v2 == fv && j2 < fj)) { fv = v2; fj = j2; }
            }
            sidx[k] = fj;
            sd2[fj] = 1e9f;
        }
        __syncthreads();
    }

    if (t < KNN) {
        int j = sidx[t];
        float vx = R[j*3]   - rx;
        float vy = R[j*3+1] - ry;
        float vz = R[j*3+2] - rz;
        float dd = sqrtf(vx*vx + vy*vy + vz*vz + 1e-12f);
        int e = i*KNN + t;
        d_idx[e] = j;
        float c = (dd <= 5.f) ? 0.5f*(cosf(0.62831853071795864769f*dd) + 1.f) : 0.f;
        d_cut[e]  = c;
        d_dist[e] = dd;
    }
}

// ---------------- QKV GEMM: (4096x128)@(128x384), 64x64 tiles, 128 thr ------
__global__ __launch_bounds__(128) void qkv_gemm(const float* __restrict__ Wq,
                                                const float* __restrict__ Wk,
                                                const float* __restrict__ Wv, int l) {
    __shared__ float As[8*64];    // [k][m]
    __shared__ float Bs[8*64];    // [k][n]
    int bm = blockIdx.x, bn = blockIdx.y, t = threadIdx.x;
    int m0 = bm * 64;
    int cb = bn * 64;
    const float* B; int ldb, coff;
    if (cb < 128)       { B = Wq + l*FDIM*FDIM; ldb = FDIM; coff = cb; }
    else if (cb < 256)  { B = Wk + l*FDIM*FDIM; ldb = FDIM; coff = cb - 128; }
    else                { B = Wv + l*FDIM*384;  ldb = 384;  coff = cb - 256; }

    int tx = t & 15;
    int ty = t >> 4;
    float acc[8][4] = {};

    for (int k0 = 0; k0 < 128; k0 += 8) {
        {
            int k = t & 7, mb = t >> 3;
            #pragma unroll
            for (int p = 0; p < 4; p++) {
                int m = mb + p*16;
                As[k*64 + m] = d_s[(m0 + m)*FDIM + k0 + k];
            }
            int kk = t >> 4, n4 = t & 15;
            *(float4*)&Bs[kk*64 + n4*4] =
                *(const float4*)&B[(k0 + kk)*ldb + coff + n4*4];
        }
        __syncthreads();
        #pragma unroll
        for (int kk = 0; kk < 8; kk++) {
            float a[8], b[4];
            #pragma unroll
            for (int x = 0; x < 8; x++) a[x] = As[kk*64 + ty*8 + x];
            #pragma unroll
            for (int x = 0; x < 4; x++) b[x] = Bs[kk*64 + tx*4 + x];
            #pragma unroll
            for (int ix = 0; ix < 8; ix++)
                #pragma unroll
                for (int jx = 0; jx < 4; jx++)
                    acc[ix][jx] = fmaf(a[ix], b[jx], acc[ix][jx]);
        }
        __syncthreads();
    }
    if (cb < 128) {
        #pragma unroll
        for (int ix = 0; ix < 8; ix++) {
            float4 v = make_float4(acc[ix][0], acc[ix][1], acc[ix][2], acc[ix][3]);
            *(float4*)&d_q[(m0 + ty*8 + ix)*FDIM + cb + tx*4] = v;
        }
    } else {
        int kcol = cb - 128;
        #pragma unroll
        for (int ix = 0; ix < 8; ix++) {
            __half2 h0 = __floats2half2_rn(acc[ix][0], acc[ix][1]);
            __half2 h1 = __floats2half2_rn(acc[ix][2], acc[ix][3]);
            __half* out = d_kvh + (size_t)(m0 + ty*8 + ix)*256 + kcol + tx*4;
            *(__half2*)(out)     = h0;
            *(__half2*)(out + 2) = h1;
        }
    }
}

// ---------------- windowed edge filter + silu -> fp16, warp-autonomous ------
#define EKV_SM_BIAS  (50*ECOL)
#define EKV_SM_EWS   (EKV_SM_BIAS + ECOL)
#define EKV_SMEM     ((EKV_SM_EWS + 8*RPAD*4) * 4)

__global__ __launch_bounds__(256, 3) void ekv_kernel(const float* __restrict__ Wek,
                                                     const float* __restrict__ bek,
                                                     const float* __restrict__ Wev,
                                                     const float* __restrict__ bev,
                                                     int l, __half* __restrict__ ekv_out) {
    extern __shared__ float sm[];
    float* Ws    = sm;
    float* biasS = sm + EKV_SM_BIAS;
    float* ews   = sm + EKV_SM_EWS;

    int tid  = threadIdx.x;
    int lane = tid & 31;
    int g    = tid >> 5;
    int eblk = blockIdx.x * EKV_EB;

    {
        float4* Ws4 = (float4*)Ws;
        const float4* Wek4 = (const float4*)(Wek + l*50*FDIM);
        const float4* Wev4 = (const float4*)(Wev + l*50*384);
        for (int q = tid; q < 50*64; q += 256) {
            int row = q >> 6;
            int c4  = q & 63;
            Ws4[q] = (c4 < 32) ? Wek4[row*32 + c4] : Wev4[row*96 + (c4 - 32)];
        }
        if (tid < 64) {
            float4 b = (tid < 32) ? ((const float4*)(bek + l*FDIM))[tid]
                                  : ((const float4*)(bev + l*384))[tid - 32];
            ((float4*)biasS)[tid] = b;
        }
    }
    __syncthreads();    // the only block-wide sync

    int c0 = lane * 4;
    float* myews = ews + g * (RPAD*4);

    float4 b0 = *(const float4*)(biasS + c0);
    float4 b1 = *(const float4*)(biasS + c0 + 128);

    #pragma unroll
    for (int pass = 0; pass < EKV_NPASS; pass++) {
        int e0 = eblk + pass*32 + g*4;

        float dd_l = 0.f, cut_l = 0.f; int k0_l = 0;
        if (lane < 4) {
            dd_l  = d_dist[e0 + lane];
            cut_l = d_cut[e0 + lane];
            float fi = dd_l * (49.0f/5.0f);
            int kk = (int)floorf(fi + 0.5f) - 7;
            k0_l = max(0, min(50 - WT, kk));
        }
        int   k0v[4]; float ddv[4], cutv[4];
        #pragma unroll
        for (int e = 0; e < 4; e++) {
            k0v[e]  = __shfl_sync(0xffffffffu, k0_l, e);
            ddv[e]  = __shfl_sync(0xffffffffu, dd_l, e);
            cutv[e] = __shfl_sync(0xffffffffu, cut_l, e);
        }
        int rmin = min(min(k0v[0], k0v[1]), min(k0v[2], k0v[3]));
        int span = max(max(k0v[0], k0v[1]), max(k0v[2], k0v[3])) + WT - rmin;

        __syncwarp();
        {
            float4 z = make_float4(0.f, 0.f, 0.f, 0.f);
            for (int r = lane; r < RPAD; r += 32)
                ((float4*)myews)[r] = z;
        }
        __syncwarp();
        #pragma unroll
        for (int u = lane; u < 64; u += 32) {
            int e = u >> 4, tt = u & 15;
            int row = k0v[e] + tt - rmin;
            float mu = (float)(k0v[e] + tt) * (5.0f/49.0f);
            float df = ddv[e] - mu;
            myews[row*4 + e] = __expf(-df*df*50.0f) * cutv[e];
        }
        __syncwarp();

        const float* wp = Ws + rmin*ECOL + c0;
        const float4* ep = (const float4*)myews;

        float4 a00 = make_float4(0,0,0,0), a01 = a00;
        float4 a10 = a00, a11 = a00;
        float4 a20 = a00, a21 = a00;
        float4 a30 = a00, a31 = a00;

        for (int r = 0; r < span; r++) {
            float4 ew = ep[r];
            float4 w0 = *(const float4*)(wp);
            float4 w1 = *(const float4*)(wp + 128);
            wp += ECOL;
            a00.x = fmaf(ew.x, w0.x, a00.x); a00.y = fmaf(ew.x, w0.y, a00.y);
            a00.z = fmaf(ew.x, w0.z, a00.z); a00.w = fmaf(ew.x, w0.w, a00.w);
            a01.x = fmaf(ew.x, w1.x, a01.x); a01.y = fmaf(ew.x, w1.y, a01.y);
            a01.z = fmaf(ew.x, w1.z, a01.z); a01.w = fmaf(ew.x, w1.w, a01.w);

            a10.x = fmaf(ew.y, w0.x, a10.x); a10.y = fmaf(ew.y, w0.y, a10.y);
            a10.z = fmaf(ew.y, w0.z, a10.z); a10.w = fmaf(ew.y, w0.w, a10.w);
            a11.x = fmaf(ew.y, w1.x, a11.x); a11.y = fmaf(ew.y, w1.y, a11.y);
            a11.z = fmaf(ew.y, w1.z, a11.z); a11.w = fmaf(ew.y, w1.w, a11.w);

            a20.x = fmaf(ew.z, w0.x, a20.x); a20.y = fmaf(ew.z, w0.y, a20.y);
            a20.z = fmaf(ew.z, w0.z, a20.z); a20.w = fmaf(ew.z, w0.w, a20.w);
            a21.x = fmaf(ew.z, w1.x, a21.x); a21.y = fmaf(ew.z, w1.y, a21.y);
            a21.z = fmaf(ew.z, w1.z, a21.z); a21.w = fmaf(ew.z, w1.w, a21.w);

            a30.x = fmaf(ew.w, w0.x, a30.x); a30.y = fmaf(ew.w, w0.y, a30.y);
            a30.z = fmaf(ew.w, w0.z, a30.z); a30.w = fmaf(ew.w, w0.w, a30.w);
            a31.x = fmaf(ew.w, w1.x, a31.x); a31.y = fmaf(ew.w, w1.y, a31.y);
            a31.z = fmaf(ew.w, w1.z, a31.z); a31.w = fmaf(ew.w, w1.w, a31.w);
        }

        float4 accs[4][2] = {{a00,a01},{a10,a11},{a20,a21},{a30,a31}};
        float4 bs[2] = {b0,b1};
        #pragma unroll
        for (int e = 0; e < 4; e++) {
            __half* out = ekv_out + (size_t)(e0 + e)*ECOL + c0;
            #pragma unroll
            for (int p = 0; p < 2; p++) {
                float4 x = accs[e][p];
                x.x += bs[p].x; x.y += bs[p].y; x.z += bs[p].z; x.w += bs[p].w;
                float s0 = x.x / (1.f + __expf(-x.x));
                float s1 = x.y / (1.f + __expf(-x.y));
                float s2 = x.z / (1.f + __expf(-x.z));
                float s3 = x.w / (1.f + __expf(-x.w));
                *(__half2*)(out + p*128)     = __floats2half2_rn(s0, s1);
                *(__half2*)(out + p*128 + 2) = __floats2half2_rn(s2, s3);
            }
        }
    }
}

// ---------------- fused attention message kernel (single gather pass) -------
__global__ void message_kernel(const __half* __restrict__ ekv) {
    __shared__ float scut[KNN];
    __shared__ float slog[KNN*NH];
    __shared__ float sattn[KNN*NH];
    __shared__ int   sj[KNN];

    int i = blockIdx.x, f = threadIdx.x;
    int w = f >> 5, lane = f & 31;

    if (f < KNN) { int e = i*KNN + f; sj[f] = d_idx[e]; scut[f] = d_cut[e]; }
    __syncthreads();

    float q = d_q[i*FDIM + f];
    float prod[KNN];

    #pragma unroll
    for (int k = 0; k < KNN; k++) {
        int j = sj[k];
        const __half* kvp = d_kvh + (size_t)j*256 + f;
        const __half* evp = ekv + (size_t)(i*KNN + k)*ECOL + f;
        float kf  = __half2float(kvp[0]);
        float va  = __half2float(kvp[128]);
        float ekf = __half2float(evp[0]);
        float ev  = __half2float(evp[128]);
        prod[k] = va * ev;
        float p = q * kf * ekf;
        #pragma unroll
        for (int off = 16; off; off >>= 1) p += __shfl_down_sync(0xffffffffu, p, off);
        if (lane == 0) slog[k*NH + w] = p * 0.125f;
    }
    __syncthreads();

    {
        float lv = (lane < KNN) ? slog[lane*NH + w] : -1e30f;
        float mx = lv;
        #pragma unroll
        for (int off = 16; off; off >>= 1) mx = fmaxf(mx, __shfl_xor_sync(0xffffffffu, mx, off));
        float ex = (lane < KNN) ? expf(lv - mx) : 0.f;
        float sm = ex;
        #pragma unroll
        for (int off = 16; off; off >>= 1) sm += __shfl_xor_sync(0xffffffffu, sm, off);
        if (lane < KNN) sattn[lane*NH + w] = ex / sm * scut[lane];
    }
    __syncthreads();

    float ds = 0.f;
    #pragma unroll
    for (int k = 0; k < KNN; k++)
        ds = fmaf(sattn[k*NH + w], prod[k], ds);
    d_s[i*FDIM + f] += ds;
    d_o[i*FDIM + f] += ds;
}

// ---------------- layernorm + readout ---------------------------------------
__global__ void readout_kernel(const float* __restrict__ ln_g, const float* __restrict__ ln_b,
                               const float* __restrict__ Wo1,  const float* __restrict__ Wo2) {
    __shared__ float red[128];
    __shared__ float son[128];
    int i = blockIdx.x, f = threadIdx.x;
    float x = d_o[i*FDIM + f];

    red[f] = x; __syncthreads();
    for (int s = 64; s > 0; s >>= 1) { if (f < s) red[f] += red[f+s]; __syncthreads(); }
    float mean = red[0] * (1.f/128.f);
    __syncthreads();

    float dx = x - mean;
    red[f] = dx*dx; __syncthreads();
    for (int s = 64; s > 0; s >>= 1) { if (f < s) red[f] += red[f+s]; __syncthreads(); }
    float var = red[0] * (1.f/128.f);
    __syncthreads();

    float on = dx * (1.f / sqrtf(var + 1e-5f)) * ln_g[f] + ln_b[f];
    son[f] = on; __syncthreads();

    float acc = 0.f;
    #pragma unroll 8
    for (int g = 0; g < 128; g++) acc = fmaf(son[g], Wo1[g*FDIM + f], acc);
    float tb = acc / (1.f + expf(-acc));
    red[f] = tb * Wo2[f];
    __syncthreads();
    for (int s = 64; s > 0; s >>= 1) { if (f < s) red[f] += red[f+s]; __syncthreads(); }
    if (f == 0) d_h[i] = red[0];
}

__global__ void sum_kernel(float* __restrict__ out) {
    __shared__ double rd[256];
    int t = threadIdx.x;
    double a = 0.0;
    for (int i = t; i < NA; i += 256) a += (double)d_h[i];
    rd[t] = a; __syncthreads();
    for (int s = 128; s > 0; s >>= 1) { if (t < s) rd[t] += rd[t+s]; __syncthreads(); }
    if (t == 0) out[0] = (float)rd[0];
}

// ---------------- launch ------------------------------------------------------
extern "C" void kernel_launch(void* const* d_in, const int* in_sizes, int n_in,
                              void* d_out, int out_size) {
    const int*   Z    = (const int*)  d_in[0];
    const float* R    = (const float*)d_in[1];
    const float* emb  = (const float*)d_in[3];
    const float* Wq   = (const float*)d_in[4];
    const float* Wk   = (const float*)d_in[5];
    const float* Wv   = (const float*)d_in[6];
    const float* We_k = (const float*)d_in[7];
    const float* be_k = (const float*)d_in[8];
    const float* We_v = (const float*)d_in[9];
    const float* be_v = (const float*)d_in[10];
    const float* ln_g = (const float*)d_in[11];
    const float* ln_b = (const float*)d_in[12];
    const float* Wo1  = (const float*)d_in[13];
    const float* Wo2  = (const float*)d_in[14];
    float* out = (float*)d_out;

    static __half* ebase = nullptr;
    static cudaStream_t s1 = nullptr;
    static cudaEvent_t evK = nullptr;
    static cudaEvent_t evE[NL];
    if (!ebase) {
        cudaGetSymbolAddress((void**)&ebase, d_ekvh);
        cudaFuncSetAttribute(ekv_kernel, cudaFuncAttributeMaxDynamicSharedMemorySize, EKV_SMEM);
        cudaStreamCreateWithFlags(&s1, cudaStreamNonBlocking);
        cudaEventCreateWithFlags(&evK, cudaEventDisableTiming);
        for (int l = 0; l < NL; l++)
            cudaEventCreateWithFlags(&evE[l], cudaEventDisableTiming);
    }

    init_kernel<<<(NA*FDIM + 255)/256, 256>>>(Z, emb);
    knn_kernel<<<NA, 256>>>(R);
    cudaEventRecord(evK, 0);

    // ekv chain: all 6 layers back-to-back on s1, own buffer each (no WAR waits)
    cudaStreamWaitEvent(s1, evK, 0);
    for (int l = 0; l < NL; l++) {
        ekv_kernel<<<NEDGE/EKV_EB, 256, EKV_SMEM, s1>>>(We_k, be_k, We_v, be_v, l,
                                                        ebase + (size_t)l*NEDGE*ECOL);
        cudaEventRecord(evE[l], s1);
    }

    for (int l = 0; l < NL; l++) {
        qkv_gemm<<<dim3(NA/64, 6), 128>>>(Wq, Wk, Wv, l);
        cudaStreamWaitEvent(0, evE[l], 0);
        message_kernel<<<NA, 128>>>(ebase + (size_t)l*NEDGE*ECOL);
    }

    readout_kernel<<<NA, 128>>>(ln_g, ln_b, Wo1, Wo2);
    sum_kernel<<<1, 256>>>(out);
}

// round 10
// speedup vs baseline: 1.0192x; 1.0192x over previous
#include <cuda_runtime.h>
#include <cuda_fp16.h>
#include <math.h>

#define NA   4096
#define FDIM 128
#define NH   4
#define DH   32
#define KNN  15
#define NKR  50
#define NL   6
#define NEDGE (NA*KNN)
#define WT   16            // RBF window taps

// ekv kernel tiling: block = 128 edges x 256 cols, warp = 4-edge group
#define EKV_EB    128
#define EKV_NPASS 4
#define RPAD      50
#define ECOL      256      // live output cols: [ek(128) | ev1(128)]

// ---------------- scratch (static device globals; no runtime alloc) --------
// The reference's vector channel v (m2/m3/vec_norm) never reaches the output
// (o only accumulates ds) — dead code, not computed.
__device__ float  d_s[NA*FDIM];
__device__ float  d_o[NA*FDIM];
__device__ float  d_q[NA*FDIM];            // fp32 q (self-read only)
__device__ __half d_kvh[NA*256];           // fp16 [k(128) | val1(128)] (gathered)
__device__ __half d_ekvh0[NEDGE*ECOL];     // fp16 [ek(128)|ev1(128)] ping
__device__ __half d_ekvh1[NEDGE*ECOL];     // fp16 pong
__device__ float  d_cut[NEDGE];
__device__ float  d_dist[NEDGE];
__device__ int    d_idx[NEDGE];
__device__ float  d_h[NA];

// ---------------- init ------------------------------------------------------
__global__ void init_kernel(const int* __restrict__ Z, const float* __restrict__ emb) {
    int t = blockIdx.x * blockDim.x + threadIdx.x;
    if (t < NA*FDIM) {
        int i = t / FDIM, f = t % FDIM;
        d_s[t] = emb[Z[i]*FDIM + f];
        d_o[t] = 0.f;
    }
}

// ---------------- KNN + edge geometry (register-resident selection) ---------
__global__ __launch_bounds__(256) void knn_kernel(const float* __restrict__ R) {
    __shared__ float swv[8];
    __shared__ int   swj[8];
    __shared__ int   sfj;
    __shared__ int   sidx[KNN];

    int i = blockIdx.x, t = threadIdx.x;
    int lane = t & 31, wrp = t >> 5;
    float rx = R[i*3], ry = R[i*3+1], rz = R[i*3+2];

    // distances for this thread's 16 atoms, kept in registers
    float dr[16];
    #pragma unroll
    for (int u = 0; u < 16; u++) {
        int j = t + u*256;
        float x = R[j*3]   - rx;
        float y = R[j*3+1] - ry;
        float z = R[j*3+2] - rz;
        float d2 = x*x + y*y + z*z;
        dr[u] = (j == i) ? 1e9f : d2;
    }

    for (int k = 0; k < KNN; k++) {
        // per-thread argmin over 16 regs (ascending u => lowest j on ties)
        float bv = 1e30f; int bu = 0;
        #pragma unroll
        for (int u = 0; u < 16; u++)
            if (dr[u] < bv) { bv = dr[u]; bu = u; }
        int bj = t + bu*256;
        // warp argmin (lowest index tie-break)
        #pragma unroll
        for (int off = 16; off; off >>= 1) {
            float v2 = __shfl_down_sync(0xffffffffu, bv, off);
            int   j2 = __shfl_down_sync(0xffffffffu, bj, off);
            if (v2 < bv || (v2 == bv && j2 < bj)) { bv = v2; bj = j2; }
        }
        if (lane == 0) { swv[wrp] = bv; swj[wrp] = bj; }
        __syncthreads();
        if (t == 0) {
            float fv = swv[0]; int fj = swj[0];
            #pragma unroll
            for (int wdx = 1; wdx < 8; wdx++) {
                float v2 = swv[wdx]; int j2 = swj[wdx];
                if (v2 < fv || (v2 == fv && j2 < fj)) { fv = v2; fj = j2; }
            }
            sidx[k] = fj;
            sfj = fj;
        }
        __syncthreads();
        int fj = sfj;
        // invalidate the winner (static unroll; no dynamic reg indexing)
        #pragma unroll
        for (int u = 0; u < 16; u++)
            if (t + u*256 == fj) dr[u] = 1e9f;
    }

    if (t < KNN) {
        int j = sidx[t];
        float vx = R[j*3]   - rx;
        float vy = R[j*3+1] - ry;
        float vz = R[j*3+2] - rz;
        float dd = sqrtf(vx*vx + vy*vy + vz*vz + 1e-12f);
        int e = i*KNN + t;
        d_idx[e] = j;
        float c = (dd <= 5.f) ? 0.5f*(cosf(0.62831853071795864769f*dd) + 1.f) : 0.f;
        d_cut[e]  = c;
        d_dist[e] = dd;
    }
}

// ---------------- QKV GEMM: (4096x128)@(128x384), 64x64 tiles, 128 thr ------
__global__ __launch_bounds__(128) void qkv_gemm(const float* __restrict__ Wq,
                                                const float* __restrict__ Wk,
                                                const float* __restrict__ Wv, int l) {
    __shared__ float As[8*64];    // [k][m]
    __shared__ float Bs[8*64];    // [k][n]
    int bm = blockIdx.x, bn = blockIdx.y, t = threadIdx.x;
    int m0 = bm * 64;
    int cb = bn * 64;
    const float* B; int ldb, coff;
    if (cb < 128)       { B = Wq + l*FDIM*FDIM; ldb = FDIM; coff = cb; }
    else if (cb < 256)  { B = Wk + l*FDIM*FDIM; ldb = FDIM; coff = cb - 128; }
    else                { B = Wv + l*FDIM*384;  ldb = 384;  coff = cb - 256; }

    int tx = t & 15;
    int ty = t >> 4;
    float acc[8][4] = {};

    for (int k0 = 0; k0 < 128; k0 += 8) {
        {
            int k = t & 7, mb = t >> 3;
            #pragma unroll
            for (int p = 0; p < 4; p++) {
                int m = mb + p*16;
                As[k*64 + m] = d_s[(m0 + m)*FDIM + k0 + k];
            }
            int kk = t >> 4, n4 = t & 15;
            *(float4*)&Bs[kk*64 + n4*4] =
                *(const float4*)&B[(k0 + kk)*ldb + coff + n4*4];
        }
        __syncthreads();
        #pragma unroll
        for (int kk = 0; kk < 8; kk++) {
            float a[8], b[4];
            #pragma unroll
            for (int x = 0; x < 8; x++) a[x] = As[kk*64 + ty*8 + x];
            #pragma unroll
            for (int x = 0; x < 4; x++) b[x] = Bs[kk*64 + tx*4 + x];
            #pragma unroll
            for (int ix = 0; ix < 8; ix++)
                #pragma unroll
                for (int jx = 0; jx < 4; jx++)
                    acc[ix][jx] = fmaf(a[ix], b[jx], acc[ix][jx]);
        }
        __syncthreads();
    }
    if (cb < 128) {
        #pragma unroll
        for (int ix = 0; ix < 8; ix++) {
            float4 v = make_float4(acc[ix][0], acc[ix][1], acc[ix][2], acc[ix][3]);
            *(float4*)&d_q[(m0 + ty*8 + ix)*FDIM + cb + tx*4] = v;
        }
    } else {
        int kcol = cb - 128;
        #pragma unroll
        for (int ix = 0; ix < 8; ix++) {
            __half2 h0 = __floats2half2_rn(acc[ix][0], acc[ix][1]);
            __half2 h1 = __floats2half2_rn(acc[ix][2], acc[ix][3]);
            __half* out = d_kvh + (size_t)(m0 + ty*8 + ix)*256 + kcol + tx*4;
            *(__half2*)(out)     = h0;
            *(__half2*)(out + 2) = h1;
        }
    }
}

// ---------------- windowed edge filter + silu -> fp16, warp-autonomous ------
#define EKV_SM_BIAS  (50*ECOL)
#define EKV_SM_EWS   (EKV_SM_BIAS + ECOL)
#define EKV_SMEM     ((EKV_SM_EWS + 8*RPAD*4) * 4)

__global__ __launch_bounds__(256, 3) void ekv_kernel(const float* __restrict__ Wek,
                                                     const float* __restrict__ bek,
                                                     const float* __restrict__ Wev,
                                                     const float* __restrict__ bev,
                                                     int l, __half* __restrict__ ekv_out) {
    extern __shared__ float sm[];
    float* Ws    = sm;
    float* biasS = sm + EKV_SM_BIAS;
    float* ews   = sm + EKV_SM_EWS;

    int tid  = threadIdx.x;
    int lane = tid & 31;
    int g    = tid >> 5;
    int eblk = blockIdx.x * EKV_EB;

    {
        float4* Ws4 = (float4*)Ws;
        const float4* Wek4 = (const float4*)(Wek + l*50*FDIM);
        const float4* Wev4 = (const float4*)(Wev + l*50*384);
        for (int q = tid; q < 50*64; q += 256) {
            int row = q >> 6;
            int c4  = q & 63;
            Ws4[q] = (c4 < 32) ? Wek4[row*32 + c4] : Wev4[row*96 + (c4 - 32)];
        }
        if (tid < 64) {
            float4 b = (tid < 32) ? ((const float4*)(bek + l*FDIM))[tid]
                                  : ((const float4*)(bev + l*384))[tid - 32];
            ((float4*)biasS)[tid] = b;
        }
    }
    __syncthreads();    // the only block-wide sync

    int c0 = lane * 4;
    float* myews = ews + g * (RPAD*4);

    float4 b0 = *(const float4*)(biasS + c0);
    float4 b1 = *(const float4*)(biasS + c0 + 128);

    #pragma unroll
    for (int pass = 0; pass < EKV_NPASS; pass++) {
        int e0 = eblk + pass*32 + g*4;

        float dd_l = 0.f, cut_l = 0.f; int k0_l = 0;
        if (lane < 4) {
            dd_l  = d_dist[e0 + lane];
            cut_l = d_cut[e0 + lane];
            float fi = dd_l * (49.0f/5.0f);
            int kk = (int)floorf(fi + 0.5f) - 7;
            k0_l = max(0, min(50 - WT, kk));
        }
        int   k0v[4]; float ddv[4], cutv[4];
        #pragma unroll
        for (int e = 0; e < 4; e++) {
            k0v[e]  = __shfl_sync(0xffffffffu, k0_l, e);
            ddv[e]  = __shfl_sync(0xffffffffu, dd_l, e);
            cutv[e] = __shfl_sync(0xffffffffu, cut_l, e);
        }
        int rmin = min(min(k0v[0], k0v[1]), min(k0v[2], k0v[3]));
        int span = max(max(k0v[0], k0v[1]), max(k0v[2], k0v[3])) + WT - rmin;

        __syncwarp();
        {
            float4 z = make_float4(0.f, 0.f, 0.f, 0.f);
            for (int r = lane; r < RPAD; r += 32)
                ((float4*)myews)[r] = z;
        }
        __syncwarp();
        #pragma unroll
        for (int u = lane; u < 64; u += 32) {
            int e = u >> 4, tt = u & 15;
            int row = k0v[e] + tt - rmin;
            float mu = (float)(k0v[e] + tt) * (5.0f/49.0f);
            float df = ddv[e] - mu;
            myews[row*4 + e] = __expf(-df*df*50.0f) * cutv[e];
        }
        __syncwarp();

        const float* wp = Ws + rmin*ECOL + c0;
        const float4* ep = (const float4*)myews;

        float4 a00 = make_float4(0,0,0,0), a01 = a00;
        float4 a10 = a00, a11 = a00;
        float4 a20 = a00, a21 = a00;
        float4 a30 = a00, a31 = a00;

        for (int r = 0; r < span; r++) {
            float4 ew = ep[r];
            float4 w0 = *(const float4*)(wp);
            float4 w1 = *(const float4*)(wp + 128);
            wp += ECOL;
            a00.x = fmaf(ew.x, w0.x, a00.x); a00.y = fmaf(ew.x, w0.y, a00.y);
            a00.z = fmaf(ew.x, w0.z, a00.z); a00.w = fmaf(ew.x, w0.w, a00.w);
            a01.x = fmaf(ew.x, w1.x, a01.x); a01.y = fmaf(ew.x, w1.y, a01.y);
            a01.z = fmaf(ew.x, w1.z, a01.z); a01.w = fmaf(ew.x, w1.w, a01.w);

            a10.x = fmaf(ew.y, w0.x, a10.x); a10.y = fmaf(ew.y, w0.y, a10.y);
            a10.z = fmaf(ew.y, w0.z, a10.z); a10.w = fmaf(ew.y, w0.w, a10.w);
            a11.x = fmaf(ew.y, w1.x, a11.x); a11.y = fmaf(ew.y, w1.y, a11.y);
            a11.z = fmaf(ew.y, w1.z, a11.z); a11.w = fmaf(ew.y, w1.w, a11.w);

            a20.x = fmaf(ew.z, w0.x, a20.x); a20.y = fmaf(ew.z, w0.y, a20.y);
            a20.z = fmaf(ew.z, w0.z, a20.z); a20.w = fmaf(ew.z, w0.w, a20.w);
            a21.x = fmaf(ew.z, w1.x, a21.x); a21.y = fmaf(ew.z, w1.y, a21.y);
            a21.z = fmaf(ew.z, w1.z, a21.z); a21.w = fmaf(ew.z, w1.w, a21.w);

            a30.x = fmaf(ew.w, w0.x, a30.x); a30.y = fmaf(ew.w, w0.y, a30.y);
            a30.z = fmaf(ew.w, w0.z, a30.z); a30.w = fmaf(ew.w, w0.w, a30.w);
            a31.x = fmaf(ew.w, w1.x, a31.x); a31.y = fmaf(ew.w, w1.y, a31.y);
            a31.z = fmaf(ew.w, w1.z, a31.z); a31.w = fmaf(ew.w, w1.w, a31.w);
        }

        float4 accs[4][2] = {{a00,a01},{a10,a11},{a20,a21},{a30,a31}};
        float4 bs[2] = {b0,b1};
        #pragma unroll
        for (int e = 0; e < 4; e++) {
            __half* out = ekv_out + (size_t)(e0 + e)*ECOL + c0;
            #pragma unroll
            for (int p = 0; p < 2; p++) {
                float4 x = accs[e][p];
                x.x += bs[p].x; x.y += bs[p].y; x.z += bs[p].z; x.w += bs[p].w;
                float s0 = x.x / (1.f + __expf(-x.x));
                float s1 = x.y / (1.f + __expf(-x.y));
                float s2 = x.z / (1.f + __expf(-x.z));
                float s3 = x.w / (1.f + __expf(-x.w));
                *(__half2*)(out + p*128)     = __floats2half2_rn(s0, s1);
                *(__half2*)(out + p*128 + 2) = __floats2half2_rn(s2, s3);
            }
        }
    }
}

// ---------------- fused attention message kernel (2 atoms per block) --------
__global__ __launch_bounds__(256) void message_kernel(const __half* __restrict__ ekv) {
    __shared__ float scut[2][KNN];
    __shared__ float slog[2][KNN*NH];
    __shared__ float sattn[2][KNN*NH];
    __shared__ int   sj[2][KNN];

    int sub = threadIdx.x >> 7;
    int f   = threadIdx.x & 127;
    int i   = blockIdx.x*2 + sub;
    int w = f >> 5, lane = f & 31;

    if (f < KNN) { int e = i*KNN + f; sj[sub][f] = d_idx[e]; scut[sub][f] = d_cut[e]; }
    __syncthreads();

    float q = d_q[i*FDIM + f];
    float prod[KNN];

    #pragma unroll
    for (int k = 0; k < KNN; k++) {
        int j = sj[sub][k];
        const __half* kvp = d_kvh + (size_t)j*256 + f;
        const __half* evp = ekv + (size_t)(i*KNN + k)*ECOL + f;
        float kf  = __half2float(kvp[0]);
        float va  = __half2float(kvp[128]);
        float ekf = __half2float(evp[0]);
        float ev  = __half2float(evp[128]);
        prod[k] = va * ev;
        float p = q * kf * ekf;
        #pragma unroll
        for (int off = 16; off; off >>= 1) p += __shfl_down_sync(0xffffffffu, p, off);
        if (lane == 0) slog[sub][k*NH + w] = p * 0.125f;
    }
    __syncthreads();

    {
        float lv = (lane < KNN) ? slog[sub][lane*NH + w] : -1e30f;
        float mx = lv;
        #pragma unroll
        for (int off = 16; off; off >>= 1) mx = fmaxf(mx, __shfl_xor_sync(0xffffffffu, mx, off));
        float ex = (lane < KNN) ? expf(lv - mx) : 0.f;
        float sm = ex;
        #pragma unroll
        for (int off = 16; off; off >>= 1) sm += __shfl_xor_sync(0xffffffffu, sm, off);
        if (lane < KNN) sattn[sub][lane*NH + w] = ex / sm * scut[sub][lane];
    }
    __syncthreads();

    float ds = 0.f;
    #pragma unroll
    for (int k = 0; k < KNN; k++)
        ds = fmaf(sattn[sub][k*NH + w], prod[k], ds);
    d_s[i*FDIM + f] += ds;
    d_o[i*FDIM + f] += ds;
}

// ---------------- layernorm + readout ---------------------------------------
__global__ void readout_kernel(const float* __restrict__ ln_g, const float* __restrict__ ln_b,
                               const float* __restrict__ Wo1,  const float* __restrict__ Wo2) {
    __shared__ float red[128];
    __shared__ float son[128];
    int i = blockIdx.x, f = threadIdx.x;
    float x = d_o[i*FDIM + f];

    red[f] = x; __syncthreads();
    for (int s = 64; s > 0; s >>= 1) { if (f < s) red[f] += red[f+s]; __syncthreads(); }
    float mean = red[0] * (1.f/128.f);
    __syncthreads();

    float dx = x - mean;
    red[f] = dx*dx; __syncthreads();
    for (int s = 64; s > 0; s >>= 1) { if (f < s) red[f] += red[f+s]; __syncthreads(); }
    float var = red[0] * (1.f/128.f);
    __syncthreads();

    float on = dx * (1.f / sqrtf(var + 1e-5f)) * ln_g[f] + ln_b[f];
    son[f] = on; __syncthreads();

    float acc = 0.f;
    #pragma unroll 8
    for (int g = 0; g < 128; g++) acc = fmaf(son[g], Wo1[g*FDIM + f], acc);
    float tb = acc / (1.f + expf(-acc));
    red[f] = tb * Wo2[f];
    __syncthreads();
    for (int s = 64; s > 0; s >>= 1) { if (f < s) red[f] += red[f+s]; __syncthreads(); }
    if (f == 0) d_h[i] = red[0];
}

__global__ void sum_kernel(float* __restrict__ out) {
    __shared__ double rd[256];
    int t = threadIdx.x;
    double a = 0.0;
    for (int i = t; i < NA; i += 256) a += (double)d_h[i];
    rd[t] = a; __syncthreads();
    for (int s = 128; s > 0; s >>= 1) { if (t < s) rd[t] += rd[t+s]; __syncthreads(); }
    if (t == 0) out[0] = (float)rd[0];
}

// ---------------- launch ------------------------------------------------------
extern "C" void kernel_launch(void* const* d_in, const int* in_sizes, int n_in,
                              void* d_out, int out_size) {
    const int*   Z    = (const int*)  d_in[0];
    const float* R    = (const float*)d_in[1];
    const float* emb  = (const float*)d_in[3];
    const float* Wq   = (const float*)d_in[4];
    const float* Wk   = (const float*)d_in[5];
    const float* Wv   = (const float*)d_in[6];
    const float* We_k = (const float*)d_in[7];
    const float* be_k = (const float*)d_in[8];
    const float* We_v = (const float*)d_in[9];
    const float* be_v = (const float*)d_in[10];
    const float* ln_g = (const float*)d_in[11];
    const float* ln_b = (const float*)d_in[12];
    const float* Wo1  = (const float*)d_in[13];
    const float* Wo2  = (const float*)d_in[14];
    float* out = (float*)d_out;

    static __half* e0p = nullptr;
    static __half* e1p = nullptr;
    static cudaStream_t s1 = nullptr;
    static cudaEvent_t evF = nullptr, evK = nullptr, evQ0 = nullptr;
    static cudaEvent_t evE[NL];
    static cudaEvent_t evM[NL];
    if (!e0p) {
        cudaGetSymbolAddress((void**)&e0p, d_ekvh0);
        cudaGetSymbolAddress((void**)&e1p, d_ekvh1);
        cudaFuncSetAttribute(ekv_kernel, cudaFuncAttributeMaxDynamicSharedMemorySize, EKV_SMEM);
        cudaStreamCreateWithFlags(&s1, cudaStreamNonBlocking);
        cudaEventCreateWithFlags(&evF, cudaEventDisableTiming);
        cudaEventCreateWithFlags(&evK, cudaEventDisableTiming);
        cudaEventCreateWithFlags(&evQ0, cudaEventDisableTiming);
        for (int l = 0; l < NL; l++) {
            cudaEventCreateWithFlags(&evE[l], cudaEventDisableTiming);
            cudaEventCreateWithFlags(&evM[l], cudaEventDisableTiming);
        }
    }
    __half* ebufs[2] = { e0p, e1p };

    // fork s1 from the captured origin stream FIRST (capture requirement)
    cudaEventRecord(evF, 0);
    cudaStreamWaitEvent(s1, evF, 0);

    // stream0: knn (needs only R).   s1: init -> qkv(0)  (hides under knn)
    knn_kernel<<<NA, 256>>>(R);
    cudaEventRecord(evK, 0);

    init_kernel<<<(NA*FDIM + 255)/256, 256, 0, s1>>>(Z, emb);
    qkv_gemm<<<dim3(NA/64, 6), 128, 0, s1>>>(Wq, Wk, Wv, 0);
    cudaEventRecord(evQ0, s1);

    // ekv chain on s1 after knn; ping-pong buffers with WAR throttling (R7)
    cudaStreamWaitEvent(s1, evK, 0);
    ekv_kernel<<<NEDGE/EKV_EB, 256, EKV_SMEM, s1>>>(We_k, be_k, We_v, be_v, 0, ebufs[0]);
    cudaEventRecord(evE[0], s1);

    for (int l = 0; l < NL; l++) {
        if (l > 0) qkv_gemm<<<dim3(NA/64, 6), 128>>>(Wq, Wk, Wv, l);
        if (l + 1 < NL) {
            if (l >= 1) cudaStreamWaitEvent(s1, evM[l-1], 0);   // WAR on ping-pong buffer
            ekv_kernel<<<NEDGE/EKV_EB, 256, EKV_SMEM, s1>>>(We_k, be_k, We_v, be_v, l + 1, ebufs[(l + 1) & 1]);
            cudaEventRecord(evE[l + 1], s1);
        }
        if (l == 0) cudaStreamWaitEvent(0, evQ0, 0);
        cudaStreamWaitEvent(0, evE[l], 0);
        message_kernel<<<NA/2, 256>>>(ebufs[l & 1]);
        cudaEventRecord(evM[l], 0);
    }

    readout_kernel<<<NA, 128>>>(ln_g, ln_b, Wo1, Wo2);
    sum_kernel<<<1, 256>>>(out);
}

// round 11
// speedup vs baseline: 1.5457x; 1.5166x over previous
#include <cuda_runtime.h>
#include <cuda_fp16.h>
#include <math.h>

#define NA   4096
#define FDIM 128
#define NH   4
#define DH   32
#define KNN  15
#define NKR  50
#define NL   6
#define NEDGE (NA*KNN)
#define WT   16            // RBF window taps
#define TROWS 4096         // table rows over d in [0,5]
#define TG_ROWS 64         // rows per tablegen block
#define ECOL  256          // table cols: [ek(128) | ev1(128)]

// ---------------- scratch (static device globals; no runtime alloc) --------
// The reference's vector channel v (m2/m3/vec_norm) never reaches the output
// (o only accumulates ds) — dead code, not computed.
// The edge filter silu(cut(d)*(RBF(d)@W_l)+b_l) is a function of the scalar d
// alone -> tabulated per layer (4096 rows, linear interp; err << fp16 rounding).
__device__ float  d_s[NA*FDIM];
__device__ float  d_o[NA*FDIM];
__device__ float  d_q[NA*FDIM];            // fp32 q (self-read only)
__device__ __half d_kvh[NA*256];           // fp16 [k(128) | val1(128)] (gathered)
__device__ __half d_tab[NL*TROWS*ECOL];    // fp16 edge-filter tables
__device__ float  d_cut[NEDGE];
__device__ float  d_dist[NEDGE];
__device__ int    d_idx[NEDGE];
__device__ float  d_h[NA];

// ---------------- init ------------------------------------------------------
__global__ void init_kernel(const int* __restrict__ Z, const float* __restrict__ emb) {
    int t = blockIdx.x * blockDim.x + threadIdx.x;
    if (t < NA*FDIM) {
        int i = t / FDIM, f = t % FDIM;
        d_s[t] = emb[Z[i]*FDIM + f];
        d_o[t] = 0.f;
    }
}

// ---------------- edge-filter table builder ---------------------------------
// block = 256 threads, builds TG_ROWS rows of layer blockIdx.y's table.
#define TG_SMEM ((50*ECOL + ECOL + TG_ROWS*16 + TG_ROWS) * 4)

__global__ __launch_bounds__(256) void tablegen_kernel(const float* __restrict__ Wek,
                                                       const float* __restrict__ bek,
                                                       const float* __restrict__ Wev,
                                                       const float* __restrict__ bev) {
    extern __shared__ float sm[];
    float* Ws    = sm;                        // 50*256
    float* biasS = sm + 50*ECOL;              // 256
    float* taps  = biasS + ECOL;              // TG_ROWS*16
    int*   kbS   = (int*)(taps + TG_ROWS*16); // TG_ROWS

    int l = blockIdx.y, rb = blockIdx.x;
    int tid = threadIdx.x;

    // weights: [We_k(128) | We_v first 128 cols]
    {
        float4* Ws4 = (float4*)Ws;
        const float4* Wek4 = (const float4*)(Wek + l*50*FDIM);
        const float4* Wev4 = (const float4*)(Wev + l*50*384);
        for (int q = tid; q < 50*64; q += 256) {
            int row = q >> 6, c4 = q & 63;
            Ws4[q] = (c4 < 32) ? Wek4[row*32 + c4] : Wev4[row*96 + (c4 - 32)];
        }
        if (tid < 64) {
            float4 b = (tid < 32) ? ((const float4*)(bek + l*FDIM))[tid]
                                  : ((const float4*)(bev + l*384))[tid - 32];
            ((float4*)biasS)[tid] = b;
        }
    }
    // taps per row (precise exp/cos: build cost is negligible)
    for (int u = tid; u < TG_ROWS*16; u += 256) {
        int r = u >> 4, t = u & 15;
        float d  = (float)(rb*TG_ROWS + r) * (5.0f/4095.0f);
        float fi = d * (49.0f/5.0f);
        int kb = (int)floorf(fi + 0.5f) - 7;
        kb = max(0, min(50 - WT, kb));
        if (t == 0) kbS[r] = kb;
        float mu  = (float)(kb + t) * (5.0f/49.0f);
        float df  = d - mu;
        float cut = 0.5f*(cosf(0.62831853071795864769f*d) + 1.0f);
        taps[u] = expf(-df*df*50.0f) * cut;
    }
    __syncthreads();

    int c = tid;
    float bias = biasS[c];
    for (int r = 0; r < TG_ROWS; r++) {
        int kb = kbS[r];
        const float* tp = taps + r*16;
        const float* wp = Ws + kb*ECOL + c;
        float acc = 0.f;
        #pragma unroll
        for (int t = 0; t < 16; t++)
            acc = fmaf(tp[t], wp[t*ECOL], acc);
        float x = acc + bias;
        float y = x / (1.f + __expf(-x));
        d_tab[((size_t)l*TROWS + rb*TG_ROWS + r)*ECOL + c] = __float2half(y);
    }
}

// ---------------- KNN + edge geometry (register-resident selection) ---------
__global__ __launch_bounds__(256) void knn_kernel(const float* __restrict__ R) {
    __shared__ float swv[8];
    __shared__ int   swj[8];
    __shared__ int   sfj;
    __shared__ int   sidx[KNN];

    int i = blockIdx.x, t = threadIdx.x;
    int lane = t & 31, wrp = t >> 5;
    float rx = R[i*3], ry = R[i*3+1], rz = R[i*3+2];

    float dr[16];
    #pragma unroll
    for (int u = 0; u < 16; u++) {
        int j = t + u*256;
        float x = R[j*3]   - rx;
        float y = R[j*3+1] - ry;
        float z = R[j*3+2] - rz;
        float d2 = x*x + y*y + z*z;
        dr[u] = (j == i) ? 1e9f : d2;
    }

    for (int k = 0; k < KNN; k++) {
        float bv = 1e30f; int bu = 0;
        #pragma unroll
        for (int u = 0; u < 16; u++)
            if (dr[u] < bv) { bv = dr[u]; bu = u; }
        int bj = t + bu*256;
        #pragma unroll
        for (int off = 16; off; off >>= 1) {
            float v2 = __shfl_down_sync(0xffffffffu, bv, off);
            int   j2 = __shfl_down_sync(0xffffffffu, bj, off);
            if (v2 < bv || (v2 == bv && j2 < bj)) { bv = v2; bj = j2; }
        }
        if (lane == 0) { swv[wrp] = bv; swj[wrp] = bj; }
        __syncthreads();
        if (t == 0) {
            float fv = swv[0]; int fj = swj[0];
            #pragma unroll
            for (int wdx = 1; wdx < 8; wdx++) {
                float v2 = swv[wdx]; int j2 = swj[wdx];
                if (v2 < fv || (v2 == fv && j2 < fj)) { fv = v2; fj = j2; }
            }
            sidx[k] = fj;
            sfj = fj;
        }
        __syncthreads();
        int fj = sfj;
        #pragma unroll
        for (int u = 0; u < 16; u++)
            if (t + u*256 == fj) dr[u] = 1e9f;
    }

    if (t < KNN) {
        int j = sidx[t];
        float vx = R[j*3]   - rx;
        float vy = R[j*3+1] - ry;
        float vz = R[j*3+2] - rz;
        float dd = sqrtf(vx*vx + vy*vy + vz*vz + 1e-12f);
        int e = i*KNN + t;
        d_idx[e] = j;
        float c = (dd <= 5.f) ? 0.5f*(cosf(0.62831853071795864769f*dd) + 1.f) : 0.f;
        d_cut[e]  = c;
        d_dist[e] = dd;
    }
}

// ---------------- QKV GEMM: (4096x128)@(128x384), 64x64 tiles, 128 thr ------
__global__ __launch_bounds__(128) void qkv_gemm(const float* __restrict__ Wq,
                                                const float* __restrict__ Wk,
                                                const float* __restrict__ Wv, int l) {
    __shared__ float As[8*64];
    __shared__ float Bs[8*64];
    int bm = blockIdx.x, bn = blockIdx.y, t = threadIdx.x;
    int m0 = bm * 64;
    int cb = bn * 64;
    const float* B; int ldb, coff;
    if (cb < 128)       { B = Wq + l*FDIM*FDIM; ldb = FDIM; coff = cb; }
    else if (cb < 256)  { B = Wk + l*FDIM*FDIM; ldb = FDIM; coff = cb - 128; }
    else                { B = Wv + l*FDIM*384;  ldb = 384;  coff = cb - 256; }

    int tx = t & 15;
    int ty = t >> 4;
    float acc[8][4] = {};

    for (int k0 = 0; k0 < 128; k0 += 8) {
        {
            int k = t & 7, mb = t >> 3;
            #pragma unroll
            for (int p = 0; p < 4; p++) {
                int m = mb + p*16;
                As[k*64 + m] = d_s[(m0 + m)*FDIM + k0 + k];
            }
            int kk = t >> 4, n4 = t & 15;
            *(float4*)&Bs[kk*64 + n4*4] =
                *(const float4*)&B[(k0 + kk)*ldb + coff + n4*4];
        }
        __syncthreads();
        #pragma unroll
        for (int kk = 0; kk < 8; kk++) {
            float a[8], b[4];
            #pragma unroll
            for (int x = 0; x < 8; x++) a[x] = As[kk*64 + ty*8 + x];
            #pragma unroll
            for (int x = 0; x < 4; x++) b[x] = Bs[kk*64 + tx*4 + x];
            #pragma unroll
            for (int ix = 0; ix < 8; ix++)
                #pragma unroll
                for (int jx = 0; jx < 4; jx++)
                    acc[ix][jx] = fmaf(a[ix], b[jx], acc[ix][jx]);
        }
        __syncthreads();
    }
    if (cb < 128) {
        #pragma unroll
        for (int ix = 0; ix < 8; ix++) {
            float4 v = make_float4(acc[ix][0], acc[ix][1], acc[ix][2], acc[ix][3]);
            *(float4*)&d_q[(m0 + ty*8 + ix)*FDIM + cb + tx*4] = v;
        }
    } else {
        int kcol = cb - 128;
        #pragma unroll
        for (int ix = 0; ix < 8; ix++) {
            __half2 h0 = __floats2half2_rn(acc[ix][0], acc[ix][1]);
            __half2 h1 = __floats2half2_rn(acc[ix][2], acc[ix][3]);
            __half* out = d_kvh + (size_t)(m0 + ty*8 + ix)*256 + kcol + tx*4;
            *(__half2*)(out)     = h0;
            *(__half2*)(out + 2) = h1;
        }
    }
}

// ---------------- fused attention message kernel (table interp) -------------
__global__ __launch_bounds__(256) void message_kernel(const __half* __restrict__ tabL) {
    __shared__ float scut[2][KNN];
    __shared__ int   si0[2][KNN];
    __shared__ float sfr[2][KNN];
    __shared__ float slog[2][KNN*NH];
    __shared__ float sattn[2][KNN*NH];
    __shared__ int   sj[2][KNN];

    int sub = threadIdx.x >> 7;
    int f   = threadIdx.x & 127;
    int i   = blockIdx.x*2 + sub;
    int w = f >> 5, lane = f & 31;

    if (f < KNN) {
        int e = i*KNN + f;
        sj[sub][f]   = d_idx[e];
        scut[sub][f] = d_cut[e];
        float fi = fminf(d_dist[e] * (4095.0f/5.0f), 4095.0f);
        int i0 = min((int)fi, 4094);
        si0[sub][f] = i0;
        sfr[sub][f] = fi - (float)i0;
    }
    __syncthreads();

    float q = d_q[i*FDIM + f];
    float prod[KNN];

    #pragma unroll
    for (int k = 0; k < KNN; k++) {
        int j = sj[sub][k];
        int i0 = si0[sub][k];
        float fr = sfr[sub][k];
        const __half* kvp = d_kvh + (size_t)j*256 + f;
        const __half* tp  = tabL + (size_t)i0*ECOL + f;
        float kf  = __half2float(kvp[0]);
        float va  = __half2float(kvp[128]);
        float ek0 = __half2float(tp[0]);
        float ev0 = __half2float(tp[128]);
        float ek1 = __half2float(tp[ECOL]);
        float ev1 = __half2float(tp[ECOL + 128]);
        float ek = fmaf(fr, ek1 - ek0, ek0);
        float ev = fmaf(fr, ev1 - ev0, ev0);
        prod[k] = va * ev;
        float p = q * kf * ek;
        #pragma unroll
        for (int off = 16; off; off >>= 1) p += __shfl_down_sync(0xffffffffu, p, off);
        if (lane == 0) slog[sub][k*NH + w] = p * 0.125f;
    }
    __syncthreads();

    {
        float lv = (lane < KNN) ? slog[sub][lane*NH + w] : -1e30f;
        float mx = lv;
        #pragma unroll
        for (int off = 16; off; off >>= 1) mx = fmaxf(mx, __shfl_xor_sync(0xffffffffu, mx, off));
        float ex = (lane < KNN) ? expf(lv - mx) : 0.f;
        float sm = ex;
        #pragma unroll
        for (int off = 16; off; off >>= 1) sm += __shfl_xor_sync(0xffffffffu, sm, off);
        if (lane < KNN) sattn[sub][lane*NH + w] = ex / sm * scut[sub][lane];
    }
    __syncthreads();

    float ds = 0.f;
    #pragma unroll
    for (int k = 0; k < KNN; k++)
        ds = fmaf(sattn[sub][k*NH + w], prod[k], ds);
    d_s[i*FDIM + f] += ds;
    d_o[i*FDIM + f] += ds;
}

// ---------------- layernorm + readout ---------------------------------------
__global__ void readout_kernel(const float* __restrict__ ln_g, const float* __restrict__ ln_b,
                               const float* __restrict__ Wo1,  const float* __restrict__ Wo2) {
    __shared__ float red[128];
    __shared__ float son[128];
    int i = blockIdx.x, f = threadIdx.x;
    float x = d_o[i*FDIM + f];

    red[f] = x; __syncthreads();
    for (int s = 64; s > 0; s >>= 1) { if (f < s) red[f] += red[f+s]; __syncthreads(); }
    float mean = red[0] * (1.f/128.f);
    __syncthreads();

    float dx = x - mean;
    red[f] = dx*dx; __syncthreads();
    for (int s = 64; s > 0; s >>= 1) { if (f < s) red[f] += red[f+s]; __syncthreads(); }
    float var = red[0] * (1.f/128.f);
    __syncthreads();

    float on = dx * (1.f / sqrtf(var + 1e-5f)) * ln_g[f] + ln_b[f];
    son[f] = on; __syncthreads();

    float acc = 0.f;
    #pragma unroll 8
    for (int g = 0; g < 128; g++) acc = fmaf(son[g], Wo1[g*FDIM + f], acc);
    float tb = acc / (1.f + expf(-acc));
    red[f] = tb * Wo2[f];
    __syncthreads();
    for (int s = 64; s > 0; s >>= 1) { if (f < s) red[f] += red[f+s]; __syncthreads(); }
    if (f == 0) d_h[i] = red[0];
}

__global__ void sum_kernel(float* __restrict__ out) {
    __shared__ double rd[256];
    int t = threadIdx.x;
    double a = 0.0;
    for (int i = t; i < NA; i += 256) a += (double)d_h[i];
    rd[t] = a; __syncthreads();
    for (int s = 128; s > 0; s >>= 1) { if (t < s) rd[t] += rd[t+s]; __syncthreads(); }
    if (t == 0) out[0] = (float)rd[0];
}

// ---------------- launch ------------------------------------------------------
extern "C" void kernel_launch(void* const* d_in, const int* in_sizes, int n_in,
                              void* d_out, int out_size) {
    const int*   Z    = (const int*)  d_in[0];
    const float* R    = (const float*)d_in[1];
    const float* emb  = (const float*)d_in[3];
    const float* Wq   = (const float*)d_in[4];
    const float* Wk   = (const float*)d_in[5];
    const float* Wv   = (const float*)d_in[6];
    const float* We_k = (const float*)d_in[7];
    const float* be_k = (const float*)d_in[8];
    const float* We_v = (const float*)d_in[9];
    const float* be_v = (const float*)d_in[10];
    const float* ln_g = (const float*)d_in[11];
    const float* ln_b = (const float*)d_in[12];
    const float* Wo1  = (const float*)d_in[13];
    const float* Wo2  = (const float*)d_in[14];
    float* out = (float*)d_out;

    static __half* tabp = nullptr;
    if (!tabp) {
        cudaGetSymbolAddress((void**)&tabp, d_tab);
        cudaFuncSetAttribute(tablegen_kernel, cudaFuncAttributeMaxDynamicSharedMemorySize, TG_SMEM);
    }

    // fully serial single-stream schedule
    tablegen_kernel<<<dim3(TROWS/TG_ROWS, NL), 256, TG_SMEM>>>(We_k, be_k, We_v, be_v);
    init_kernel<<<(NA*FDIM + 255)/256, 256>>>(Z, emb);
    knn_kernel<<<NA, 256>>>(R);

    for (int l = 0; l < NL; l++) {
        qkv_gemm<<<dim3(NA/64, 6), 128>>>(Wq, Wk, Wv, l);
        message_kernel<<<NA/2, 256>>>(tabp + (size_t)l*TROWS*ECOL);
    }

    readout_kernel<<<NA, 128>>>(ln_g, ln_b, Wo1, Wo2);
    sum_kernel<<<1, 256>>>(out);
}

// round 12
// speedup vs baseline: 1.5735x; 1.0180x over previous
#include <cuda_runtime.h>
#include <cuda_fp16.h>
#include <math.h>

#define NA   4096
#define FDIM 128
#define NH   4
#define DH   32
#define KNN  15
#define NKR  50
#define NL   6
#define NEDGE (NA*KNN)
#define WT   16            // RBF window taps
#define TROWS 4096         // table rows over d in [0,5]
#define TG_ROWS 64         // rows per tablegen block
#define ECOL  256          // table cols: [ek(128) | ev1(128)]

// ---------------- scratch (static device globals; no runtime alloc) --------
// The reference's vector channel v (m2/m3/vec_norm) never reaches the output
// (o only accumulates ds) — dead code, not computed.
// The edge filter silu(cut(d)*(RBF(d)@W_l)+b_l) is a function of the scalar d
// alone -> tabulated per layer (4096 rows, linear interp; err << fp16 rounding).
__device__ float  d_s[NA*FDIM];
__device__ float  d_o[NA*FDIM];
__device__ float  d_q[NA*FDIM];            // fp32 q (self-read only)
__device__ __half d_kvh[NA*256];           // fp16 [k(128) | val1(128)] (gathered)
__device__ __half d_tab[NL*TROWS*ECOL];    // fp16 edge-filter tables
__device__ float  d_cut[NEDGE];
__device__ float  d_dist[NEDGE];
__device__ int    d_idx[NEDGE];
__device__ float  d_h[NA];

// ---------------- init ------------------------------------------------------
__global__ void init_kernel(const int* __restrict__ Z, const float* __restrict__ emb) {
    int t = blockIdx.x * blockDim.x + threadIdx.x;
    if (t < NA*FDIM) {
        int i = t / FDIM, f = t % FDIM;
        d_s[t] = emb[Z[i]*FDIM + f];
        d_o[t] = 0.f;
    }
}

// ---------------- edge-filter table builder ---------------------------------
#define TG_SMEM ((50*ECOL + ECOL + TG_ROWS*16 + TG_ROWS) * 4)

__global__ __launch_bounds__(256) void tablegen_kernel(const float* __restrict__ Wek,
                                                       const float* __restrict__ bek,
                                                       const float* __restrict__ Wev,
                                                       const float* __restrict__ bev) {
    extern __shared__ float sm[];
    float* Ws    = sm;                        // 50*256
    float* biasS = sm + 50*ECOL;              // 256
    float* taps  = biasS + ECOL;              // TG_ROWS*16
    int*   kbS   = (int*)(taps + TG_ROWS*16); // TG_ROWS

    int l = blockIdx.y, rb = blockIdx.x;
    int tid = threadIdx.x;

    {
        float4* Ws4 = (float4*)Ws;
        const float4* Wek4 = (const float4*)(Wek + l*50*FDIM);
        const float4* Wev4 = (const float4*)(Wev + l*50*384);
        for (int q = tid; q < 50*64; q += 256) {
            int row = q >> 6, c4 = q & 63;
            Ws4[q] = (c4 < 32) ? Wek4[row*32 + c4] : Wev4[row*96 + (c4 - 32)];
        }
        if (tid < 64) {
            float4 b = (tid < 32) ? ((const float4*)(bek + l*FDIM))[tid]
                                  : ((const float4*)(bev + l*384))[tid - 32];
            ((float4*)biasS)[tid] = b;
        }
    }
    for (int u = tid; u < TG_ROWS*16; u += 256) {
        int r = u >> 4, t = u & 15;
        float d  = (float)(rb*TG_ROWS + r) * (5.0f/4095.0f);
        float fi = d * (49.0f/5.0f);
        int kb = (int)floorf(fi + 0.5f) - 7;
        kb = max(0, min(50 - WT, kb));
        if (t == 0) kbS[r] = kb;
        float mu  = (float)(kb + t) * (5.0f/49.0f);
        float df  = d - mu;
        float cut = 0.5f*(cosf(0.62831853071795864769f*d) + 1.0f);
        taps[u] = expf(-df*df*50.0f) * cut;
    }
    __syncthreads();

    int c = tid;
    float bias = biasS[c];
    for (int r = 0; r < TG_ROWS; r++) {
        int kb = kbS[r];
        const float* tp = taps + r*16;
        const float* wp = Ws + kb*ECOL + c;
        float acc = 0.f;
        #pragma unroll
        for (int t = 0; t < 16; t++)
            acc = fmaf(tp[t], wp[t*ECOL], acc);
        float x = acc + bias;
        float y = x / (1.f + __expf(-x));
        d_tab[((size_t)l*TROWS + rb*TG_ROWS + r)*ECOL + c] = __float2half(y);
    }
}

// ---------------- KNN + edge geometry (register-resident selection) ---------
__global__ __launch_bounds__(256) void knn_kernel(const float* __restrict__ R) {
    __shared__ float swv[8];
    __shared__ int   swj[8];
    __shared__ int   sfj;
    __shared__ int   sidx[KNN];

    int i = blockIdx.x, t = threadIdx.x;
    int lane = t & 31, wrp = t >> 5;
    float rx = R[i*3], ry = R[i*3+1], rz = R[i*3+2];

    float dr[16];
    #pragma unroll
    for (int u = 0; u < 16; u++) {
        int j = t + u*256;
        float x = R[j*3]   - rx;
        float y = R[j*3+1] - ry;
        float z = R[j*3+2] - rz;
        float d2 = x*x + y*y + z*z;
        dr[u] = (j == i) ? 1e9f : d2;
    }

    for (int k = 0; k < KNN; k++) {
        float bv = 1e30f; int bu = 0;
        #pragma unroll
        for (int u = 0; u < 16; u++)
            if (dr[u] < bv) { bv = dr[u]; bu = u; }
        int bj = t + bu*256;
        #pragma unroll
        for (int off = 16; off; off >>= 1) {
            float v2 = __shfl_down_sync(0xffffffffu, bv, off);
            int   j2 = __shfl_down_sync(0xffffffffu, bj, off);
            if (v2 < bv || (v2 == bv && j2 < bj)) { bv = v2; bj = j2; }
        }
        if (lane == 0) { swv[wrp] = bv; swj[wrp] = bj; }
        __syncthreads();
        if (t == 0) {
            float fv = swv[0]; int fj = swj[0];
            #pragma unroll
            for (int wdx = 1; wdx < 8; wdx++) {
                float v2 = swv[wdx]; int j2 = swj[wdx];
                if (v2 < fv || (v2 == fv && j2 < fj)) { fv = v2; fj = j2; }
            }
            sidx[k] = fj;
            sfj = fj;
        }
        __syncthreads();
        int fj = sfj;
        #pragma unroll
        for (int u = 0; u < 16; u++)
            if (t + u*256 == fj) dr[u] = 1e9f;
    }

    if (t < KNN) {
        int j = sidx[t];
        float vx = R[j*3]   - rx;
        float vy = R[j*3+1] - ry;
        float vz = R[j*3+2] - rz;
        float dd = sqrtf(vx*vx + vy*vy + vz*vz + 1e-12f);
        int e = i*KNN + t;
        d_idx[e] = j;
        float c = (dd <= 5.f) ? 0.5f*(cosf(0.62831853071795864769f*dd) + 1.f) : 0.f;
        d_cut[e]  = c;
        d_dist[e] = dd;
    }
}

// ---------------- QKV GEMM: 32x64 tiles, 128 thr, 4x4/thread ----------------
__global__ __launch_bounds__(128) void qkv_gemm(const float* __restrict__ Wq,
                                                const float* __restrict__ Wk,
                                                const float* __restrict__ Wv, int l) {
    __shared__ float As[8*32];    // [k][m]
    __shared__ float Bs[8*64];    // [k][n]
    int bm = blockIdx.x, bn = blockIdx.y, t = threadIdx.x;
    int m0 = bm * 32;
    int cb = bn * 64;
    const float* B; int ldb, coff;
    if (cb < 128)       { B = Wq + l*FDIM*FDIM; ldb = FDIM; coff = cb; }
    else if (cb < 256)  { B = Wk + l*FDIM*FDIM; ldb = FDIM; coff = cb - 128; }
    else                { B = Wv + l*FDIM*384;  ldb = 384;  coff = cb - 256; }

    int tx = t & 15;      // n group: 4 cols
    int ty = t >> 4;      // m group: 4 rows (0..7)
    float acc[4][4] = {};

    for (int k0 = 0; k0 < 128; k0 += 8) {
        {
            int k = t & 7, mb = t >> 3;     // mb 0..15
            As[k*32 + mb]      = d_s[(m0 + mb)*FDIM + k0 + k];
            As[k*32 + mb + 16] = d_s[(m0 + mb + 16)*FDIM + k0 + k];
            int kk = t >> 4, n4 = t & 15;
            *(float4*)&Bs[kk*64 + n4*4] =
                *(const float4*)&B[(k0 + kk)*ldb + coff + n4*4];
        }
        __syncthreads();
        #pragma unroll
        for (int kk = 0; kk < 8; kk++) {
            float4 a = *(const float4*)&As[kk*32 + ty*4];
            float4 b = *(const float4*)&Bs[kk*64 + tx*4];
            float av[4] = {a.x, a.y, a.z, a.w};
            float bv[4] = {b.x, b.y, b.z, b.w};
            #pragma unroll
            for (int ix = 0; ix < 4; ix++)
                #pragma unroll
                for (int jx = 0; jx < 4; jx++)
                    acc[ix][jx] = fmaf(av[ix], bv[jx], acc[ix][jx]);
        }
        __syncthreads();
    }
    if (cb < 128) {
        #pragma unroll
        for (int ix = 0; ix < 4; ix++) {
            float4 v = make_float4(acc[ix][0], acc[ix][1], acc[ix][2], acc[ix][3]);
            *(float4*)&d_q[(m0 + ty*4 + ix)*FDIM + cb + tx*4] = v;
        }
    } else {
        int kcol = cb - 128;
        #pragma unroll
        for (int ix = 0; ix < 4; ix++) {
            __half2 h0 = __floats2half2_rn(acc[ix][0], acc[ix][1]);
            __half2 h1 = __floats2half2_rn(acc[ix][2], acc[ix][3]);
            __half* out = d_kvh + (size_t)(m0 + ty*4 + ix)*256 + kcol + tx*4;
            *(__half2*)(out)     = h0;
            *(__half2*)(out + 2) = h1;
        }
    }
}

// ---------------- fused attention message kernel (table interp, 4 atoms) ----
__global__ __launch_bounds__(512) void message_kernel(const __half* __restrict__ tabL) {
    __shared__ float scut[4][KNN];
    __shared__ int   si0[4][KNN];
    __shared__ float sfr[4][KNN];
    __shared__ float slog[4][KNN*NH];
    __shared__ float sattn[4][KNN*NH];
    __shared__ int   sj[4][KNN];

    int sub = threadIdx.x >> 7;
    int f   = threadIdx.x & 127;
    int i   = blockIdx.x*4 + sub;
    int w = f >> 5, lane = f & 31;

    if (f < KNN) {
        int e = i*KNN + f;
        sj[sub][f]   = d_idx[e];
        scut[sub][f] = d_cut[e];
        float fi = fminf(d_dist[e] * (4095.0f/5.0f), 4095.0f);
        int i0 = min((int)fi, 4094);
        si0[sub][f] = i0;
        sfr[sub][f] = fi - (float)i0;
    }
    __syncthreads();

    float q = d_q[i*FDIM + f];
    float prod[KNN];

    #pragma unroll
    for (int k = 0; k < KNN; k++) {
        int j = sj[sub][k];
        int i0 = si0[sub][k];
        float fr = sfr[sub][k];
        const __half* kvp = d_kvh + (size_t)j*256 + f;
        const __half* tp  = tabL + (size_t)i0*ECOL + f;
        float kf  = __half2float(kvp[0]);
        float va  = __half2float(kvp[128]);
        float ek0 = __half2float(tp[0]);
        float ev0 = __half2float(tp[128]);
        float ek1 = __half2float(tp[ECOL]);
        float ev1 = __half2float(tp[ECOL + 128]);
        float ek = fmaf(fr, ek1 - ek0, ek0);
        float ev = fmaf(fr, ev1 - ev0, ev0);
        prod[k] = va * ev;
        float p = q * kf * ek;
        #pragma unroll
        for (int off = 16; off; off >>= 1) p += __shfl_down_sync(0xffffffffu, p, off);
        if (lane == 0) slog[sub][k*NH + w] = p * 0.125f;
    }
    __syncthreads();

    {
        float lv = (lane < KNN) ? slog[sub][lane*NH + w] : -1e30f;
        float mx = lv;
        #pragma unroll
        for (int off = 16; off; off >>= 1) mx = fmaxf(mx, __shfl_xor_sync(0xffffffffu, mx, off));
        float ex = (lane < KNN) ? expf(lv - mx) : 0.f;
        float sm = ex;
        #pragma unroll
        for (int off = 16; off; off >>= 1) sm += __shfl_xor_sync(0xffffffffu, sm, off);
        if (lane < KNN) sattn[sub][lane*NH + w] = ex / sm * scut[sub][lane];
    }
    __syncthreads();

    float ds = 0.f;
    #pragma unroll
    for (int k = 0; k < KNN; k++)
        ds = fmaf(sattn[sub][k*NH + w], prod[k], ds);
    d_s[i*FDIM + f] += ds;
    d_o[i*FDIM + f] += ds;
}

// ---------------- layernorm + readout ---------------------------------------
__global__ void readout_kernel(const float* __restrict__ ln_g, const float* __restrict__ ln_b,
                               const float* __restrict__ Wo1,  const float* __restrict__ Wo2) {
    __shared__ float red[128];
    __shared__ float son[128];
    int i = blockIdx.x, f = threadIdx.x;
    float x = d_o[i*FDIM + f];

    red[f] = x; __syncthreads();
    for (int s = 64; s > 0; s >>= 1) { if (f < s) red[f] += red[f+s]; __syncthreads(); }
    float mean = red[0] * (1.f/128.f);
    __syncthreads();

    float dx = x - mean;
    red[f] = dx*dx; __syncthreads();
    for (int s = 64; s > 0; s >>= 1) { if (f < s) red[f] += red[f+s]; __syncthreads(); }
    float var = red[0] * (1.f/128.f);
    __syncthreads();

    float on = dx * (1.f / sqrtf(var + 1e-5f)) * ln_g[f] + ln_b[f];
    son[f] = on; __syncthreads();

    float acc = 0.f;
    #pragma unroll 8
    for (int g = 0; g < 128; g++) acc = fmaf(son[g], Wo1[g*FDIM + f], acc);
    float tb = acc / (1.f + expf(-acc));
    red[f] = tb * Wo2[f];
    __syncthreads();
    for (int s = 64; s > 0; s >>= 1) { if (f < s) red[f] += red[f+s]; __syncthreads(); }
    if (f == 0) d_h[i] = red[0];
}

__global__ void sum_kernel(float* __restrict__ out) {
    __shared__ double rd[256];
    int t = threadIdx.x;
    double a = 0.0;
    for (int i = t; i < NA; i += 256) a += (double)d_h[i];
    rd[t] = a; __syncthreads();
    for (int s = 128; s > 0; s >>= 1) { if (t < s) rd[t] += rd[t+s]; __syncthreads(); }
    if (t == 0) out[0] = (float)rd[0];
}

// ---------------- launch ------------------------------------------------------
extern "C" void kernel_launch(void* const* d_in, const int* in_sizes, int n_in,
                              void* d_out, int out_size) {
    const int*   Z    = (const int*)  d_in[0];
    const float* R    = (const float*)d_in[1];
    const float* emb  = (const float*)d_in[3];
    const float* Wq   = (const float*)d_in[4];
    const float* Wk   = (const float*)d_in[5];
    const float* Wv   = (const float*)d_in[6];
    const float* We_k = (const float*)d_in[7];
    const float* be_k = (const float*)d_in[8];
    const float* We_v = (const float*)d_in[9];
    const float* be_v = (const float*)d_in[10];
    const float* ln_g = (const float*)d_in[11];
    const float* ln_b = (const float*)d_in[12];
    const float* Wo1  = (const float*)d_in[13];
    const float* Wo2  = (const float*)d_in[14];
    float* out = (float*)d_out;

    static __half* tabp = nullptr;
    static cudaStream_t s1 = nullptr;
    static cudaEvent_t evF = nullptr, evT = nullptr;
    if (!tabp) {
        cudaGetSymbolAddress((void**)&tabp, d_tab);
        cudaFuncSetAttribute(tablegen_kernel, cudaFuncAttributeMaxDynamicSharedMemorySize, TG_SMEM);
        cudaStreamCreateWithFlags(&s1, cudaStreamNonBlocking);
        cudaEventCreateWithFlags(&evF, cudaEventDisableTiming);
        cudaEventCreateWithFlags(&evT, cudaEventDisableTiming);
    }

    // fork s1 from captured origin stream (capture requirement), run tablegen there
    cudaEventRecord(evF, 0);
    cudaStreamWaitEvent(s1, evF, 0);
    tablegen_kernel<<<dim3(TROWS/TG_ROWS, NL), 256, TG_SMEM, s1>>>(We_k, be_k, We_v, be_v);
    cudaEventRecord(evT, s1);

    // stream0: init, knn, qkv(0) — independent of tables
    init_kernel<<<(NA*FDIM + 255)/256, 256>>>(Z, emb);
    knn_kernel<<<NA, 256>>>(R);
    cudaStreamWaitEvent(0, evT, 0);   // join before first message

    for (int l = 0; l < NL; l++) {
        qkv_gemm<<<dim3(NA/32, 6), 128>>>(Wq, Wk, Wv, l);
        message_kernel<<<NA/4, 512>>>(tabp + (size_t)l*TROWS*ECOL);
    }

    readout_kernel<<<NA, 128>>>(ln_g, ln_b, Wo1, Wo2);
    sum_kernel<<<1, 256>>>(out);
}

// round 13
// speedup vs baseline: 1.7874x; 1.1359x over previous
#include <cuda_runtime.h>
#include <cuda_fp16.h>
#include <math.h>

#define NA   4096
#define FDIM 128
#define NH   4
#define DH   32
#define KNN  15
#define NKR  50
#define NL   6
#define NEDGE (NA*KNN)
#define WT   16
#define TROWS 4096
#define TG_ROWS 64
#define ECOL  256          // table cols: [ek(128) | ev1(128)]
#define NQKV  384          // q(128) | k(128) | val1(128)

// ---------------- scratch (static device globals; no runtime alloc) --------
// Dead code eliminated: reference's vector channel v never reaches the output.
// Edge filter tabulated over scalar d (4096 rows/layer, lerp).
// QKV via m16n8k16 HMMA: s kept fp32 master + fp16 shadow; W pre-permuted to
// B-fragment layout once per run.
__device__ float  d_s[NA*FDIM];
__device__ __half d_sh[NA*FDIM];           // fp16 shadow of s (HMMA A operand)
__device__ float  d_o[NA*FDIM];
__device__ float  d_q[NA*FDIM];
__device__ __half d_kvh[NA*256];           // fp16 [k(128) | val1(128)]
__device__ __half d_tab[NL*TROWS*ECOL];
__device__ uint2  d_w16[NL*48*8*32];       // B-fragments: [l][nblk8][kblk16][lane]
__device__ float  d_cut[NEDGE];
__device__ float  d_dist[NEDGE];
__device__ int    d_idx[NEDGE];
__device__ float  d_h[NA];

// ---------------- init ------------------------------------------------------
__global__ void init_kernel(const int* __restrict__ Z, const float* __restrict__ emb) {
    int t = blockIdx.x * blockDim.x + threadIdx.x;
    if (t < NA*FDIM) {
        int i = t / FDIM, f = t % FDIM;
        float v = emb[Z[i]*FDIM + f];
        d_s[t]  = v;
        d_sh[t] = __float2half(v);
        d_o[t]  = 0.f;
    }
}

// ---------------- weight converter: fp32 -> fp16 B-fragment layout ----------
// element idx = ((l*48 + nblk)*8 + kblk)*32 + lane;  lane: n = nblk*8 + lane/4,
// k0 = kblk*16 + (lane%4)*2; frag = {W[k0][n],W[k0+1][n],W[k0+8][n],W[k0+9][n]}
__global__ void wcvt_kernel(const float* __restrict__ Wq, const float* __restrict__ Wk,
                            const float* __restrict__ Wv) {
    int t = blockIdx.x*256 + threadIdx.x;
    if (t >= NL*48*8*32) return;
    int lane = t & 31;
    int kblk = (t >> 5) & 7;
    int nblk = (t >> 8) % 48;
    int l    = t / (48*8*32);
    int n  = nblk*8 + (lane >> 2);
    int k0 = kblk*16 + (lane & 3)*2;

    float w[4];
    #pragma unroll
    for (int j = 0; j < 4; j++) {
        int k = k0 + (j >> 1)*8 + (j & 1);
        float v;
        if (n < 128)      v = Wq[l*FDIM*FDIM + k*FDIM + n];
        else if (n < 256) v = Wk[l*FDIM*FDIM + k*FDIM + (n - 128)];
        else              v = Wv[l*FDIM*384  + k*384  + (n - 256)];
        w[j] = v;
    }
    uint2 out;
    out.x = __half2_raw(__floats2half2_rn(w[0], w[1])).x |
            ((unsigned)__half2_raw(__floats2half2_rn(w[0], w[1])).y << 16);
    out.y = __half2_raw(__floats2half2_rn(w[2], w[3])).x |
            ((unsigned)__half2_raw(__floats2half2_rn(w[2], w[3])).y << 16);
    // simpler: reinterpret
    __half2 h0 = __floats2half2_rn(w[0], w[1]);
    __half2 h1 = __floats2half2_rn(w[2], w[3]);
    out.x = *(unsigned*)&h0;
    out.y = *(unsigned*)&h1;
    d_w16[t] = out;
}

// ---------------- edge-filter table builder ---------------------------------
#define TG_SMEM ((50*ECOL + ECOL + TG_ROWS*16 + TG_ROWS) * 4)

__global__ __launch_bounds__(256) void tablegen_kernel(const float* __restrict__ Wek,
                                                       const float* __restrict__ bek,
                                                       const float* __restrict__ Wev,
                                                       const float* __restrict__ bev) {
    extern __shared__ float sm[];
    float* Ws    = sm;
    float* biasS = sm + 50*ECOL;
    float* taps  = biasS + ECOL;
    int*   kbS   = (int*)(taps + TG_ROWS*16);

    int l = blockIdx.y, rb = blockIdx.x;
    int tid = threadIdx.x;

    {
        float4* Ws4 = (float4*)Ws;
        const float4* Wek4 = (const float4*)(Wek + l*50*FDIM);
        const float4* Wev4 = (const float4*)(Wev + l*50*384);
        for (int q = tid; q < 50*64; q += 256) {
            int row = q >> 6, c4 = q & 63;
            Ws4[q] = (c4 < 32) ? Wek4[row*32 + c4] : Wev4[row*96 + (c4 - 32)];
        }
        if (tid < 64) {
            float4 b = (tid < 32) ? ((const float4*)(bek + l*FDIM))[tid]
                                  : ((const float4*)(bev + l*384))[tid - 32];
            ((float4*)biasS)[tid] = b;
        }
    }
    for (int u = tid; u < TG_ROWS*16; u += 256) {
        int r = u >> 4, t = u & 15;
        float d  = (float)(rb*TG_ROWS + r) * (5.0f/4095.0f);
        float fi = d * (49.0f/5.0f);
        int kb = (int)floorf(fi + 0.5f) - 7;
        kb = max(0, min(50 - WT, kb));
        if (t == 0) kbS[r] = kb;
        float mu  = (float)(kb + t) * (5.0f/49.0f);
        float df  = d - mu;
        float cut = 0.5f*(cosf(0.62831853071795864769f*d) + 1.0f);
        taps[u] = expf(-df*df*50.0f) * cut;
    }
    __syncthreads();

    int c = tid;
    float bias = biasS[c];
    for (int r = 0; r < TG_ROWS; r++) {
        int kb = kbS[r];
        const float* tp = taps + r*16;
        const float* wp = Ws + kb*ECOL + c;
        float acc = 0.f;
        #pragma unroll
        for (int t = 0; t < 16; t++)
            acc = fmaf(tp[t], wp[t*ECOL], acc);
        float x = acc + bias;
        float y = x / (1.f + __expf(-x));
        d_tab[((size_t)l*TROWS + rb*TG_ROWS + r)*ECOL + c] = __float2half(y);
    }
}

// ---------------- KNN + edge geometry (register-resident selection) ---------
__global__ __launch_bounds__(256) void knn_kernel(const float* __restrict__ R) {
    __shared__ float swv[8];
    __shared__ int   swj[8];
    __shared__ int   sfj;
    __shared__ int   sidx[KNN];

    int i = blockIdx.x, t = threadIdx.x;
    int lane = t & 31, wrp = t >> 5;
    float rx = R[i*3], ry = R[i*3+1], rz = R[i*3+2];

    float dr[16];
    #pragma unroll
    for (int u = 0; u < 16; u++) {
        int j = t + u*256;
        float x = R[j*3]   - rx;
        float y = R[j*3+1] - ry;
        float z = R[j*3+2] - rz;
        float d2 = x*x + y*y + z*z;
        dr[u] = (j == i) ? 1e9f : d2;
    }

    for (int k = 0; k < KNN; k++) {
        float bv = 1e30f; int bu = 0;
        #pragma unroll
        for (int u = 0; u < 16; u++)
            if (dr[u] < bv) { bv = dr[u]; bu = u; }
        int bj = t + bu*256;
        #pragma unroll
        for (int off = 16; off; off >>= 1) {
            float v2 = __shfl_down_sync(0xffffffffu, bv, off);
            int   j2 = __shfl_down_sync(0xffffffffu, bj, off);
            if (v2 < bv || (v2 == bv && j2 < bj)) { bv = v2; bj = j2; }
        }
        if (lane == 0) { swv[wrp] = bv; swj[wrp] = bj; }
        __syncthreads();
        if (t == 0) {
            float fv = swv[0]; int fj = swj[0];
            #pragma unroll
            for (int wdx = 1; wdx < 8; wdx++) {
                float v2 = swv[wdx]; int j2 = swj[wdx];
                if (v2 < fv || (v2 == fv && j2 < fj)) { fv = v2; fj = j2; }
            }
            sidx[k] = fj;
            sfj = fj;
        }
        __syncthreads();
        int fj = sfj;
        #pragma unroll
        for (int u = 0; u < 16; u++)
            if (t + u*256 == fj) dr[u] = 1e9f;
    }

    if (t < KNN) {
        int j = sidx[t];
        float vx = R[j*3]   - rx;
        float vy = R[j*3+1] - ry;
        float vz = R[j*3+2] - rz;
        float dd = sqrtf(vx*vx + vy*vy + vz*vz + 1e-12f);
        int e = i*KNN + t;
        d_idx[e] = j;
        float c = (dd <= 5.f) ? 0.5f*(cosf(0.62831853071795864769f*dd) + 1.f) : 0.f;
        d_cut[e]  = c;
        d_dist[e] = dd;
    }
}

// ---------------- QKV via m16n8k16 HMMA (fp16 in, fp32 acc, no smem) --------
__global__ __launch_bounds__(128) void qkv_mma(int l) {
    int bm = blockIdx.x, bn = blockIdx.y;     // bm: 64-row tile; bn: 64-col tile
    int wm = threadIdx.x >> 5, lane = threadIdx.x & 31;
    int r0 = bm*64 + wm*16 + (lane >> 2);
    int c0 = (lane & 3)*2;

    // A fragments for all 8 k-blocks (rows r0, r0+8)
    unsigned A[8][4];
    #pragma unroll
    for (int kb = 0; kb < 8; kb++) {
        const __half* p0 = d_sh + r0*FDIM + kb*16 + c0;
        const __half* p1 = d_sh + (r0+8)*FDIM + kb*16 + c0;
        A[kb][0] = *(const unsigned*)p0;
        A[kb][1] = *(const unsigned*)p1;
        A[kb][2] = *(const unsigned*)(p0 + 8);
        A[kb][3] = *(const unsigned*)(p1 + 8);
    }

    const uint2* Wp = d_w16 + ((size_t)(l*48 + bn*8) * 8) * 32;

    #pragma unroll
    for (int nb = 0; nb < 8; nb++) {
        float f0 = 0.f, f1 = 0.f, f2 = 0.f, f3 = 0.f;
        #pragma unroll
        for (int kb = 0; kb < 8; kb++) {
            uint2 bv = Wp[(nb*8 + kb)*32 + lane];
            asm volatile(
                "mma.sync.aligned.m16n8k16.row.col.f32.f16.f16.f32 "
                "{%0,%1,%2,%3}, {%4,%5,%6,%7}, {%8,%9}, {%0,%1,%2,%3};"
                : "+f"(f0), "+f"(f1), "+f"(f2), "+f"(f3)
                : "r"(A[kb][0]), "r"(A[kb][1]), "r"(A[kb][2]), "r"(A[kb][3]),
                  "r"(bv.x), "r"(bv.y));
        }
        int ngl = bn*64 + nb*8 + c0;
        if (ngl < 128) {
            *(float2*)&d_q[r0*FDIM + ngl]     = make_float2(f0, f1);
            *(float2*)&d_q[(r0+8)*FDIM + ngl] = make_float2(f2, f3);
        } else {
            int kc = ngl - 128;
            *(__half2*)&d_kvh[(size_t)r0*256 + kc]     = __floats2half2_rn(f0, f1);
            *(__half2*)&d_kvh[(size_t)(r0+8)*256 + kc] = __floats2half2_rn(f2, f3);
        }
    }
}

// ---------------- fused attention message kernel (table interp, 4 atoms) ----
__global__ __launch_bounds__(512) void message_kernel(const __half* __restrict__ tabL) {
    __shared__ float scut[4][KNN];
    __shared__ int   si0[4][KNN];
    __shared__ float sfr[4][KNN];
    __shared__ float slog[4][KNN*NH];
    __shared__ float sattn[4][KNN*NH];
    __shared__ int   sj[4][KNN];

    int sub = threadIdx.x >> 7;
    int f   = threadIdx.x & 127;
    int i   = blockIdx.x*4 + sub;
    int w = f >> 5, lane = f & 31;

    if (f < KNN) {
        int e = i*KNN + f;
        sj[sub][f]   = d_idx[e];
        scut[sub][f] = d_cut[e];
        float fi = fminf(d_dist[e] * (4095.0f/5.0f), 4095.0f);
        int i0 = min((int)fi, 4094);
        si0[sub][f] = i0;
        sfr[sub][f] = fi - (float)i0;
    }
    __syncthreads();

    float q = d_q[i*FDIM + f];
    float prod[KNN];

    #pragma unroll
    for (int k = 0; k < KNN; k++) {
        int j = sj[sub][k];
        int i0 = si0[sub][k];
        float fr = sfr[sub][k];
        const __half* kvp = d_kvh + (size_t)j*256 + f;
        const __half* tp  = tabL + (size_t)i0*ECOL + f;
        float kf  = __half2float(kvp[0]);
        float va  = __half2float(kvp[128]);
        float ek0 = __half2float(tp[0]);
        float ev0 = __half2float(tp[128]);
        float ek1 = __half2float(tp[ECOL]);
        float ev1 = __half2float(tp[ECOL + 128]);
        float ek = fmaf(fr, ek1 - ek0, ek0);
        float ev = fmaf(fr, ev1 - ev0, ev0);
        prod[k] = va * ev;
        float p = q * kf * ek;
        #pragma unroll
        for (int off = 16; off; off >>= 1) p += __shfl_down_sync(0xffffffffu, p, off);
        if (lane == 0) slog[sub][k*NH + w] = p * 0.125f;
    }
    __syncthreads();

    {
        float lv = (lane < KNN) ? slog[sub][lane*NH + w] : -1e30f;
        float mx = lv;
        #pragma unroll
        for (int off = 16; off; off >>= 1) mx = fmaxf(mx, __shfl_xor_sync(0xffffffffu, mx, off));
        float ex = (lane < KNN) ? expf(lv - mx) : 0.f;
        float sm = ex;
        #pragma unroll
        for (int off = 16; off; off >>= 1) sm += __shfl_xor_sync(0xffffffffu, sm, off);
        if (lane < KNN) sattn[sub][lane*NH + w] = ex / sm * scut[sub][lane];
    }
    __syncthreads();

    float ds = 0.f;
    #pragma unroll
    for (int k = 0; k < KNN; k++)
        ds = fmaf(sattn[sub][k*NH + w], prod[k], ds);
    float sn = d_s[i*FDIM + f] + ds;
    d_s[i*FDIM + f]  = sn;
    d_sh[i*FDIM + f] = __float2half(sn);
    d_o[i*FDIM + f] += ds;
}

// ---------------- layernorm + readout ---------------------------------------
__global__ void readout_kernel(const float* __restrict__ ln_g, const float* __restrict__ ln_b,
                               const float* __restrict__ Wo1,  const float* __restrict__ Wo2) {
    __shared__ float red[128];
    __shared__ float son[128];
    int i = blockIdx.x, f = threadIdx.x;
    float x = d_o[i*FDIM + f];

    red[f] = x; __syncthreads();
    for (int s = 64; s > 0; s >>= 1) { if (f < s) red[f] += red[f+s]; __syncthreads(); }
    float mean = red[0] * (1.f/128.f);
    __syncthreads();

    float dx = x - mean;
    red[f] = dx*dx; __syncthreads();
    for (int s = 64; s > 0; s >>= 1) { if (f < s) red[f] += red[f+s]; __syncthreads(); }
    float var = red[0] * (1.f/128.f);
    __syncthreads();

    float on = dx * (1.f / sqrtf(var + 1e-5f)) * ln_g[f] + ln_b[f];
    son[f] = on; __syncthreads();

    float acc = 0.f;
    #pragma unroll 8
    for (int g = 0; g < 128; g++) acc = fmaf(son[g], Wo1[g*FDIM + f], acc);
    float tb = acc / (1.f + expf(-acc));
    red[f] = tb * Wo2[f];
    __syncthreads();
    for (int s = 64; s > 0; s >>= 1) { if (f < s) red[f] += red[f+s]; __syncthreads(); }
    if (f == 0) d_h[i] = red[0];
}

__global__ void sum_kernel(float* __restrict__ out) {
    __shared__ double rd[256];
    int t = threadIdx.x;
    double a = 0.0;
    for (int i = t; i < NA; i += 256) a += (double)d_h[i];
    rd[t] = a; __syncthreads();
    for (int s = 128; s > 0; s >>= 1) { if (t < s) rd[t] += rd[t+s]; __syncthreads(); }
    if (t == 0) out[0] = (float)rd[0];
}

// ---------------- launch ------------------------------------------------------
extern "C" void kernel_launch(void* const* d_in, const int* in_sizes, int n_in,
                              void* d_out, int out_size) {
    const int*   Z    = (const int*)  d_in[0];
    const float* R    = (const float*)d_in[1];
    const float* emb  = (const float*)d_in[3];
    const float* Wq   = (const float*)d_in[4];
    const float* Wk   = (const float*)d_in[5];
    const float* Wv   = (const float*)d_in[6];
    const float* We_k = (const float*)d_in[7];
    const float* be_k = (const float*)d_in[8];
    const float* We_v = (const float*)d_in[9];
    const float* be_v = (const float*)d_in[10];
    const float* ln_g = (const float*)d_in[11];
    const float* ln_b = (const float*)d_in[12];
    const float* Wo1  = (const float*)d_in[13];
    const float* Wo2  = (const float*)d_in[14];
    float* out = (float*)d_out;

    static __half* tabp = nullptr;
    static cudaStream_t s1 = nullptr;
    static cudaEvent_t evF = nullptr, evT = nullptr;
    if (!tabp) {
        cudaGetSymbolAddress((void**)&tabp, d_tab);
        cudaFuncSetAttribute(tablegen_kernel, cudaFuncAttributeMaxDynamicSharedMemorySize, TG_SMEM);
        cudaStreamCreateWithFlags(&s1, cudaStreamNonBlocking);
        cudaEventCreateWithFlags(&evF, cudaEventDisableTiming);
        cudaEventCreateWithFlags(&evT, cudaEventDisableTiming);
    }

    // fork s1 (capture-safe), run tablegen + weight conversion there
    cudaEventRecord(evF, 0);
    cudaStreamWaitEvent(s1, evF, 0);
    tablegen_kernel<<<dim3(TROWS/TG_ROWS, NL), 256, TG_SMEM, s1>>>(We_k, be_k, We_v, be_v);
    wcvt_kernel<<<(NL*48*8*32 + 255)/256, 256, 0, s1>>>(Wq, Wk, Wv);
    cudaEventRecord(evT, s1);

    // stream0: init, knn — independent of tables/weights
    init_kernel<<<(NA*FDIM + 255)/256, 256>>>(Z, emb);
    knn_kernel<<<NA, 256>>>(R);
    cudaStreamWaitEvent(0, evT, 0);   // join before layer loop

    for (int l = 0; l < NL; l++) {
        qkv_mma<<<dim3(NA/64, 6), 128>>>(l);
        message_kernel<<<NA/4, 512>>>(tabp + (size_t)l*TROWS*ECOL);
    }

    readout_kernel<<<NA, 128>>>(ln_g, ln_b, Wo1, Wo2);
    sum_kernel<<<1, 256>>>(out);
}

// round 14
// speedup vs baseline: 2.1938x; 1.2273x over previous
#include <cuda_runtime.h>
#include <cuda_fp16.h>
#include <math.h>

#define NA   4096
#define FDIM 128
#define NH   4
#define DH   32
#define KNN  15
#define NKR  50
#define NL   6
#define NEDGE (NA*KNN)
#define WT   16
#define TROWS 4096
#define TG_ROWS 64
#define ECOL  256          // table cols: [ek(128) | ev1(128)]

// ---------------- scratch (static device globals; no runtime alloc) --------
// Dead code eliminated: reference's vector channel v never reaches the output.
// Edge filter tabulated over scalar d (4096 rows/layer, lerp).
// QKV via m16n8k16 HMMA; KNN via histogram radix-select.
__device__ float  d_s[NA*FDIM];
__device__ __half d_sh[NA*FDIM];           // fp16 shadow of s (HMMA A operand)
__device__ float  d_o[NA*FDIM];
__device__ float  d_q[NA*FDIM];
__device__ __half d_kvh[NA*256];           // fp16 [k(128) | val1(128)]
__device__ __half d_tab[NL*TROWS*ECOL];
__device__ uint2  d_w16[NL*48*8*32];       // B-fragments: [l][nblk8][kblk16][lane]
__device__ float  d_cut[NEDGE];
__device__ float  d_dist[NEDGE];
__device__ int    d_idx[NEDGE];
__device__ float  d_h[NA];

// ---------------- init ------------------------------------------------------
__global__ void init_kernel(const int* __restrict__ Z, const float* __restrict__ emb) {
    int t = blockIdx.x * blockDim.x + threadIdx.x;
    if (t < NA*FDIM) {
        int i = t / FDIM, f = t % FDIM;
        float v = emb[Z[i]*FDIM + f];
        d_s[t]  = v;
        d_sh[t] = __float2half(v);
        d_o[t]  = 0.f;
    }
}

// ---------------- weight converter: fp32 -> fp16 B-fragment layout ----------
__global__ void wcvt_kernel(const float* __restrict__ Wq, const float* __restrict__ Wk,
                            const float* __restrict__ Wv) {
    int t = blockIdx.x*256 + threadIdx.x;
    if (t >= NL*48*8*32) return;
    int lane = t & 31;
    int kblk = (t >> 5) & 7;
    int nblk = (t >> 8) % 48;
    int l    = t / (48*8*32);
    int n  = nblk*8 + (lane >> 2);
    int k0 = kblk*16 + (lane & 3)*2;

    float w[4];
    #pragma unroll
    for (int j = 0; j < 4; j++) {
        int k = k0 + (j >> 1)*8 + (j & 1);
        float v;
        if (n < 128)      v = Wq[l*FDIM*FDIM + k*FDIM + n];
        else if (n < 256) v = Wk[l*FDIM*FDIM + k*FDIM + (n - 128)];
        else              v = Wv[l*FDIM*384  + k*384  + (n - 256)];
        w[j] = v;
    }
    __half2 h0 = __floats2half2_rn(w[0], w[1]);
    __half2 h1 = __floats2half2_rn(w[2], w[3]);
    uint2 out;
    out.x = *(unsigned*)&h0;
    out.y = *(unsigned*)&h1;
    d_w16[t] = out;
}

// ---------------- edge-filter table builder ---------------------------------
#define TG_SMEM ((50*ECOL + ECOL + TG_ROWS*16 + TG_ROWS) * 4)

__global__ __launch_bounds__(256) void tablegen_kernel(const float* __restrict__ Wek,
                                                       const float* __restrict__ bek,
                                                       const float* __restrict__ Wev,
                                                       const float* __restrict__ bev) {
    extern __shared__ float sm[];
    float* Ws    = sm;
    float* biasS = sm + 50*ECOL;
    float* taps  = biasS + ECOL;
    int*   kbS   = (int*)(taps + TG_ROWS*16);

    int l = blockIdx.y, rb = blockIdx.x;
    int tid = threadIdx.x;

    {
        float4* Ws4 = (float4*)Ws;
        const float4* Wek4 = (const float4*)(Wek + l*50*FDIM);
        const float4* Wev4 = (const float4*)(Wev + l*50*384);
        for (int q = tid; q < 50*64; q += 256) {
            int row = q >> 6, c4 = q & 63;
            Ws4[q] = (c4 < 32) ? Wek4[row*32 + c4] : Wev4[row*96 + (c4 - 32)];
        }
        if (tid < 64) {
            float4 b = (tid < 32) ? ((const float4*)(bek + l*FDIM))[tid]
                                  : ((const float4*)(bev + l*384))[tid - 32];
            ((float4*)biasS)[tid] = b;
        }
    }
    for (int u = tid; u < TG_ROWS*16; u += 256) {
        int r = u >> 4, t = u & 15;
        float d  = (float)(rb*TG_ROWS + r) * (5.0f/4095.0f);
        float fi = d * (49.0f/5.0f);
        int kb = (int)floorf(fi + 0.5f) - 7;
        kb = max(0, min(50 - WT, kb));
        if (t == 0) kbS[r] = kb;
        float mu  = (float)(kb + t) * (5.0f/49.0f);
        float df  = d - mu;
        float cut = 0.5f*(cosf(0.62831853071795864769f*d) + 1.0f);
        taps[u] = expf(-df*df*50.0f) * cut;
    }
    __syncthreads();

    int c = tid;
    float bias = biasS[c];
    for (int r = 0; r < TG_ROWS; r++) {
        int kb = kbS[r];
        const float* tp = taps + r*16;
        const float* wp = Ws + kb*ECOL + c;
        float acc = 0.f;
        #pragma unroll
        for (int t = 0; t < 16; t++)
            acc = fmaf(tp[t], wp[t*ECOL], acc);
        float x = acc + bias;
        float y = x / (1.f + __expf(-x));
        d_tab[((size_t)l*TROWS + rb*TG_ROWS + r)*ECOL + c] = __float2half(y);
    }
}

// ---------------- KNN via histogram radix-select ----------------------------
#define KNN_CAP 128

__global__ __launch_bounds__(256) void knn_kernel(const float* __restrict__ R) {
    __shared__ int   hist[256];
    __shared__ int   warpsum[8];
    __shared__ int   s_cutbin;
    __shared__ int   s_cnt;
    __shared__ float cv[KNN_CAP];
    __shared__ int   cjj[KNN_CAP];
    __shared__ int   sidx[KNN];

    int i = blockIdx.x, t = threadIdx.x;
    int lane = t & 31, wrp = t >> 5;
    float rx = R[i*3], ry = R[i*3+1], rz = R[i*3+2];

    float dr[16];
    int   bn[16];
    hist[t] = 0;
    if (t == 0) s_cnt = 0;
    __syncthreads();

    #pragma unroll
    for (int u = 0; u < 16; u++) {
        int j = t + u*256;
        float x = R[j*3]   - rx;
        float y = R[j*3+1] - ry;
        float z = R[j*3+2] - rz;
        float d2 = x*x + y*y + z*z;
        if (j == i) d2 = 1e9f;
        dr[u] = d2;
        int b = (int)fminf(d2 * 0.25f, 255.0f);
        bn[u] = b;
        atomicAdd(&hist[b], 1);
    }
    __syncthreads();

    // inclusive scan of per-warp chunk (32 bins each), chunk sums to warpsum
    {
        int h = hist[t];
        int sc = h;
        #pragma unroll
        for (int off = 1; off < 32; off <<= 1) {
            int o = __shfl_up_sync(0xffffffffu, sc, off);
            if (lane >= off) sc += o;
        }
        if (lane == 31) warpsum[wrp] = sc;
    }
    __syncthreads();
    if (t == 0) {
        int acc = 0, cw = 7;
        #pragma unroll
        for (int w = 0; w < 8; w++) {
            if (acc + warpsum[w] >= KNN) { cw = w; break; }
            acc += warpsum[w];
        }
        int cum = acc, cutbin = cw*32 + 31;
        for (int b = cw*32; b < cw*32 + 32; b++) {
            int hb = hist[b];
            if (cum + hb >= KNN) { cutbin = b; break; }
            cum += hb;
        }
        s_cutbin = cutbin;
    }
    __syncthreads();

    int cutbin = s_cutbin;
    #pragma unroll
    for (int u = 0; u < 16; u++) {
        if (bn[u] <= cutbin) {
            int p = atomicAdd(&s_cnt, 1);
            if (p < KNN_CAP) { cv[p] = dr[u]; cjj[p] = t + u*256; }
        }
    }
    __syncthreads();
    int cnt = min(s_cnt, KNN_CAP);

    // warp 0 selects the 15 smallest (lowest index on ties) from the candidates
    if (wrp == 0) {
        for (int k = 0; k < KNN; k++) {
            float bv = 1e30f; int bj = 0x7fffffff, bp = -1;
            for (int p = lane; p < cnt; p += 32) {
                float v = cv[p]; int j = cjj[p];
                if (v < bv || (v == bv && j < bj)) { bv = v; bj = j; bp = p; }
            }
            #pragma unroll
            for (int off = 16; off; off >>= 1) {
                float v2 = __shfl_down_sync(0xffffffffu, bv, off);
                int   j2 = __shfl_down_sync(0xffffffffu, bj, off);
                int   p2 = __shfl_down_sync(0xffffffffu, bp, off);
                if (v2 < bv || (v2 == bv && j2 < bj)) { bv = v2; bj = j2; bp = p2; }
            }
            bp = __shfl_sync(0xffffffffu, bp, 0);
            if (lane == 0) { sidx[k] = bj; cv[bp] = 1e30f; }
            __syncwarp();
        }
    }
    __syncthreads();

    if (t < KNN) {
        int j = sidx[t];
        float vx = R[j*3]   - rx;
        float vy = R[j*3+1] - ry;
        float vz = R[j*3+2] - rz;
        float dd = sqrtf(vx*vx + vy*vy + vz*vz + 1e-12f);
        int e = i*KNN + t;
        d_idx[e] = j;
        float c = (dd <= 5.f) ? 0.5f*(cosf(0.62831853071795864769f*dd) + 1.f) : 0.f;
        d_cut[e]  = c;
        d_dist[e] = dd;
    }
}

// ---------------- QKV via m16n8k16 HMMA (fp16 in, fp32 acc, no smem) --------
__global__ __launch_bounds__(128) void qkv_mma(int l) {
    int bm = blockIdx.x, bn = blockIdx.y;
    int wm = threadIdx.x >> 5, lane = threadIdx.x & 31;
    int r0 = bm*64 + wm*16 + (lane >> 2);
    int c0 = (lane & 3)*2;

    unsigned A[8][4];
    #pragma unroll
    for (int kb = 0; kb < 8; kb++) {
        const __half* p0 = d_sh + r0*FDIM + kb*16 + c0;
        const __half* p1 = d_sh + (r0+8)*FDIM + kb*16 + c0;
        A[kb][0] = *(const unsigned*)p0;
        A[kb][1] = *(const unsigned*)p1;
        A[kb][2] = *(const unsigned*)(p0 + 8);
        A[kb][3] = *(const unsigned*)(p1 + 8);
    }

    const uint2* Wp = d_w16 + ((size_t)(l*48 + bn*8) * 8) * 32;

    #pragma unroll
    for (int nb = 0; nb < 8; nb++) {
        float f0 = 0.f, f1 = 0.f, f2 = 0.f, f3 = 0.f;
        #pragma unroll
        for (int kb = 0; kb < 8; kb++) {
            uint2 bv = Wp[(nb*8 + kb)*32 + lane];
            asm volatile(
                "mma.sync.aligned.m16n8k16.row.col.f32.f16.f16.f32 "
                "{%0,%1,%2,%3}, {%4,%5,%6,%7}, {%8,%9}, {%0,%1,%2,%3};"
                : "+f"(f0), "+f"(f1), "+f"(f2), "+f"(f3)
                : "r"(A[kb][0]), "r"(A[kb][1]), "r"(A[kb][2]), "r"(A[kb][3]),
                  "r"(bv.x), "r"(bv.y));
        }
        int ngl = bn*64 + nb*8 + c0;
        if (ngl < 128) {
            *(float2*)&d_q[r0*FDIM + ngl]     = make_float2(f0, f1);
            *(float2*)&d_q[(r0+8)*FDIM + ngl] = make_float2(f2, f3);
        } else {
            int kc = ngl - 128;
            *(__half2*)&d_kvh[(size_t)r0*256 + kc]     = __floats2half2_rn(f0, f1);
            *(__half2*)&d_kvh[(size_t)(r0+8)*256 + kc] = __floats2half2_rn(f2, f3);
        }
    }
}

// ---------------- fused attention message kernel (table interp, 4 atoms) ----
__global__ __launch_bounds__(512) void message_kernel(const __half* __restrict__ tabL) {
    __shared__ float scut[4][KNN];
    __shared__ int   si0[4][KNN];
    __shared__ float sfr[4][KNN];
    __shared__ float slog[4][KNN*NH];
    __shared__ float sattn[4][KNN*NH];
    __shared__ int   sj[4][KNN];

    int sub = threadIdx.x >> 7;
    int f   = threadIdx.x & 127;
    int i   = blockIdx.x*4 + sub;
    int w = f >> 5, lane = f & 31;

    if (f < KNN) {
        int e = i*KNN + f;
        sj[sub][f]   = d_idx[e];
        scut[sub][f] = d_cut[e];
        float fi = fminf(d_dist[e] * (4095.0f/5.0f), 4095.0f);
        int i0 = min((int)fi, 4094);
        si0[sub][f] = i0;
        sfr[sub][f] = fi - (float)i0;
    }
    __syncthreads();

    float q = d_q[i*FDIM + f];
    float prod[KNN];

    #pragma unroll
    for (int k = 0; k < KNN; k++) {
        int j = sj[sub][k];
        int i0 = si0[sub][k];
        float fr = sfr[sub][k];
        const __half* kvp = d_kvh + (size_t)j*256 + f;
        const __half* tp  = tabL + (size_t)i0*ECOL + f;
        float kf  = __half2float(kvp[0]);
        float va  = __half2float(kvp[128]);
        float ek0 = __half2float(tp[0]);
        float ev0 = __half2float(tp[128]);
        float ek1 = __half2float(tp[ECOL]);
        float ev1 = __half2float(tp[ECOL + 128]);
        float ek = fmaf(fr, ek1 - ek0, ek0);
        float ev = fmaf(fr, ev1 - ev0, ev0);
        prod[k] = va * ev;
        float p = q * kf * ek;
        #pragma unroll
        for (int off = 16; off; off >>= 1) p += __shfl_down_sync(0xffffffffu, p, off);
        if (lane == 0) slog[sub][k*NH + w] = p * 0.125f;
    }
    __syncthreads();

    {
        float lv = (lane < KNN) ? slog[sub][lane*NH + w] : -1e30f;
        float mx = lv;
        #pragma unroll
        for (int off = 16; off; off >>= 1) mx = fmaxf(mx, __shfl_xor_sync(0xffffffffu, mx, off));
        float ex = (lane < KNN) ? expf(lv - mx) : 0.f;
        float sm = ex;
        #pragma unroll
        for (int off = 16; off; off >>= 1) sm += __shfl_xor_sync(0xffffffffu, sm, off);
        if (lane < KNN) sattn[sub][lane*NH + w] = ex / sm * scut[sub][lane];
    }
    __syncthreads();

    float ds = 0.f;
    #pragma unroll
    for (int k = 0; k < KNN; k++)
        ds = fmaf(sattn[sub][k*NH + w], prod[k], ds);
    float sn = d_s[i*FDIM + f] + ds;
    d_s[i*FDIM + f]  = sn;
    d_sh[i*FDIM + f] = __float2half(sn);
    d_o[i*FDIM + f] += ds;
}

// ---------------- layernorm + readout ---------------------------------------
__global__ void readout_kernel(const float* __restrict__ ln_g, const float* __restrict__ ln_b,
                               const float* __restrict__ Wo1,  const float* __restrict__ Wo2) {
    __shared__ float red[128];
    __shared__ float son[128];
    int i = blockIdx.x, f = threadIdx.x;
    float x = d_o[i*FDIM + f];

    red[f] = x; __syncthreads();
    for (int s = 64; s > 0; s >>= 1) { if (f < s) red[f] += red[f+s]; __syncthreads(); }
    float mean = red[0] * (1.f/128.f);
    __syncthreads();

    float dx = x - mean;
    red[f] = dx*dx; __syncthreads();
    for (int s = 64; s > 0; s >>= 1) { if (f < s) red[f] += red[f+s]; __syncthreads(); }
    float var = red[0] * (1.f/128.f);
    __syncthreads();

    float on = dx * (1.f / sqrtf(var + 1e-5f)) * ln_g[f] + ln_b[f];
    son[f] = on; __syncthreads();

    float acc = 0.f;
    #pragma unroll 8
    for (int g = 0; g < 128; g++) acc = fmaf(son[g], Wo1[g*FDIM + f], acc);
    float tb = acc / (1.f + expf(-acc));
    red[f] = tb * Wo2[f];
    __syncthreads();
    for (int s = 64; s > 0; s >>= 1) { if (f < s) red[f] += red[f+s]; __syncthreads(); }
    if (f == 0) d_h[i] = red[0];
}

__global__ void sum_kernel(float* __restrict__ out) {
    __shared__ double rd[256];
    int t = threadIdx.x;
    double a = 0.0;
    for (int i = t; i < NA; i += 256) a += (double)d_h[i];
    rd[t] = a; __syncthreads();
    for (int s = 128; s > 0; s >>= 1) { if (t < s) rd[t] += rd[t+s]; __syncthreads(); }
    if (t == 0) out[0] = (float)rd[0];
}

// ---------------- launch ------------------------------------------------------
extern "C" void kernel_launch(void* const* d_in, const int* in_sizes, int n_in,
                              void* d_out, int out_size) {
    const int*   Z    = (const int*)  d_in[0];
    const float* R    = (const float*)d_in[1];
    const float* emb  = (const float*)d_in[3];
    const float* Wq   = (const float*)d_in[4];
    const float* Wk   = (const float*)d_in[5];
    const float* Wv   = (const float*)d_in[6];
    const float* We_k = (const float*)d_in[7];
    const float* be_k = (const float*)d_in[8];
    const float* We_v = (const float*)d_in[9];
    const float* be_v = (const float*)d_in[10];
    const float* ln_g = (const float*)d_in[11];
    const float* ln_b = (const float*)d_in[12];
    const float* Wo1  = (const float*)d_in[13];
    const float* Wo2  = (const float*)d_in[14];
    float* out = (float*)d_out;

    static __half* tabp = nullptr;
    static cudaStream_t s1 = nullptr;
    static cudaEvent_t evF = nullptr, evT = nullptr;
    if (!tabp) {
        cudaGetSymbolAddress((void**)&tabp, d_tab);
        cudaFuncSetAttribute(tablegen_kernel, cudaFuncAttributeMaxDynamicSharedMemorySize, TG_SMEM);
        cudaStreamCreateWithFlags(&s1, cudaStreamNonBlocking);
        cudaEventCreateWithFlags(&evF, cudaEventDisableTiming);
        cudaEventCreateWithFlags(&evT, cudaEventDisableTiming);
    }

    // fork s1 (capture-safe), run tablegen + weight conversion there
    cudaEventRecord(evF, 0);
    cudaStreamWaitEvent(s1, evF, 0);
    tablegen_kernel<<<dim3(TROWS/TG_ROWS, NL), 256, TG_SMEM, s1>>>(We_k, be_k, We_v, be_v);
    wcvt_kernel<<<(NL*48*8*32 + 255)/256, 256, 0, s1>>>(Wq, Wk, Wv);
    cudaEventRecord(evT, s1);

    // stream0: init, knn — independent of tables/weights
    init_kernel<<<(NA*FDIM + 255)/256, 256>>>(Z, emb);
    knn_kernel<<<NA, 256>>>(R);
    cudaStreamWaitEvent(0, evT, 0);   // join before layer loop

    for (int l = 0; l < NL; l++) {
        qkv_mma<<<dim3(NA/64, 6), 128>>>(l);
        message_kernel<<<NA/4, 512>>>(tabp + (size_t)l*TROWS*ECOL);
    }

    readout_kernel<<<NA, 128>>>(ln_g, ln_b, Wo1, Wo2);
    sum_kernel<<<1, 256>>>(out);
}

// round 15
// speedup vs baseline: 2.6109x; 1.1901x over previous
#include <cuda_runtime.h>
#include <cuda_fp16.h>
#include <math.h>

#define NA   4096
#define FDIM 128
#define NH   4
#define DH   32
#define KNN  15
#define NKR  50
#define NL   6
#define NEDGE (NA*KNN)
#define WT   16
#define TROWS 4096
#define TG_ROWS 64
#define ECOL  256          // table cols, interleaved: [ (ek_c, ev_c) x 128 ]

// ---------------- scratch (static device globals; no runtime alloc) --------
// Dead code eliminated: reference's vector channel v never reaches the output.
// Edge filter tabulated over scalar d (4096 rows/layer, lerp), (ek,ev) interleaved.
// QKV via m16n8k16 HMMA; KNN via histogram radix-select with parallel rank.
__device__ float  d_s[NA*FDIM];
__device__ __half d_sh[NA*FDIM];           // fp16 shadow of s (HMMA A operand)
__device__ float  d_o[NA*FDIM];
__device__ float  d_q[NA*FDIM];
__device__ __half d_kvh[NA*256];           // fp16 interleaved (k_f, val_f) pairs
__device__ __half d_tab[NL*TROWS*ECOL];    // fp16 interleaved (ek_f, ev_f) pairs
__device__ uint2  d_w16[NL*48*8*32];       // B-fragments: [l][nblk8][kblk16][lane]
__device__ float  d_cut[NEDGE];
__device__ float  d_dist[NEDGE];
__device__ int    d_idx[NEDGE];
__device__ float  d_h[NA];

// ---------------- init ------------------------------------------------------
__global__ void init_kernel(const int* __restrict__ Z, const float* __restrict__ emb) {
    int t = blockIdx.x * blockDim.x + threadIdx.x;
    if (t < NA*FDIM) {
        int i = t / FDIM, f = t % FDIM;
        float v = emb[Z[i]*FDIM + f];
        d_s[t]  = v;
        d_sh[t] = __float2half(v);
        d_o[t]  = 0.f;
    }
}

// ---------------- weight converter: fp32 -> fp16 B-fragment layout ----------
__global__ void wcvt_kernel(const float* __restrict__ Wq, const float* __restrict__ Wk,
                            const float* __restrict__ Wv) {
    int t = blockIdx.x*256 + threadIdx.x;
    if (t >= NL*48*8*32) return;
    int lane = t & 31;
    int kblk = (t >> 5) & 7;
    int nblk = (t >> 8) % 48;
    int l    = t / (48*8*32);
    int n  = nblk*8 + (lane >> 2);
    int k0 = kblk*16 + (lane & 3)*2;

    float w[4];
    #pragma unroll
    for (int j = 0; j < 4; j++) {
        int k = k0 + (j >> 1)*8 + (j & 1);
        float v;
        if (n < 128)      v = Wq[l*FDIM*FDIM + k*FDIM + n];
        else if (n < 256) v = Wk[l*FDIM*FDIM + k*FDIM + (n - 128)];
        else              v = Wv[l*FDIM*384  + k*384  + (n - 256)];
        w[j] = v;
    }
    __half2 h0 = __floats2half2_rn(w[0], w[1]);
    __half2 h1 = __floats2half2_rn(w[2], w[3]);
    uint2 out;
    out.x = *(unsigned*)&h0;
    out.y = *(unsigned*)&h1;
    d_w16[t] = out;
}

// ---------------- edge-filter table builder (interleaved output) ------------
#define TG_SMEM ((50*ECOL + ECOL + TG_ROWS*16 + TG_ROWS) * 4)

__global__ __launch_bounds__(256) void tablegen_kernel(const float* __restrict__ Wek,
                                                       const float* __restrict__ bek,
                                                       const float* __restrict__ Wev,
                                                       const float* __restrict__ bev) {
    extern __shared__ float sm[];
    float* Ws    = sm;
    float* biasS = sm + 50*ECOL;
    float* taps  = biasS + ECOL;
    int*   kbS   = (int*)(taps + TG_ROWS*16);

    int l = blockIdx.y, rb = blockIdx.x;
    int tid = threadIdx.x;

    {
        float4* Ws4 = (float4*)Ws;
        const float4* Wek4 = (const float4*)(Wek + l*50*FDIM);
        const float4* Wev4 = (const float4*)(Wev + l*50*384);
        for (int q = tid; q < 50*64; q += 256) {
            int row = q >> 6, c4 = q & 63;
            Ws4[q] = (c4 < 32) ? Wek4[row*32 + c4] : Wev4[row*96 + (c4 - 32)];
        }
        if (tid < 64) {
            float4 b = (tid < 32) ? ((const float4*)(bek + l*FDIM))[tid]
                                  : ((const float4*)(bev + l*384))[tid - 32];
            ((float4*)biasS)[tid] = b;
        }
    }
    for (int u = tid; u < TG_ROWS*16; u += 256) {
        int r = u >> 4, t = u & 15;
        float d  = (float)(rb*TG_ROWS + r) * (5.0f/4095.0f);
        float fi = d * (49.0f/5.0f);
        int kb = (int)floorf(fi + 0.5f) - 7;
        kb = max(0, min(50 - WT, kb));
        if (t == 0) kbS[r] = kb;
        float mu  = (float)(kb + t) * (5.0f/49.0f);
        float df  = d - mu;
        float cut = 0.5f*(cosf(0.62831853071795864769f*d) + 1.0f);
        taps[u] = expf(-df*df*50.0f) * cut;
    }
    __syncthreads();

    int c = tid;
    float bias = biasS[c];
    // interleaved destination: col c<128 (ek) -> 2c ; col c>=128 (ev) -> 2(c-128)+1
    int dst = (c < 128) ? (2*c) : (2*(c - 128) + 1);
    for (int r = 0; r < TG_ROWS; r++) {
        int kb = kbS[r];
        const float* tp = taps + r*16;
        const float* wp = Ws + kb*ECOL + c;
        float acc = 0.f;
        #pragma unroll
        for (int t = 0; t < 16; t++)
            acc = fmaf(tp[t], wp[t*ECOL], acc);
        float x = acc + bias;
        float y = x / (1.f + __expf(-x));
        d_tab[((size_t)l*TROWS + rb*TG_ROWS + r)*ECOL + dst] = __float2half(y);
    }
}

// ---------------- KNN via histogram radix-select (parallel rank) ------------
#define KNN_CAP 128

__global__ __launch_bounds__(256) void knn_kernel(const float* __restrict__ R) {
    __shared__ int   hist[256];
    __shared__ int   warpsum[8];
    __shared__ int   s_cutbin;
    __shared__ int   s_cnt;
    __shared__ float cv[KNN_CAP];
    __shared__ int   cjj[KNN_CAP];
    __shared__ int   sidx[KNN];

    int i = blockIdx.x, t = threadIdx.x;
    int lane = t & 31, wrp = t >> 5;
    float rx = R[i*3], ry = R[i*3+1], rz = R[i*3+2];

    float dr[16];
    int   bn[16];
    hist[t] = 0;
    if (t == 0) s_cnt = 0;
    __syncthreads();

    #pragma unroll
    for (int u = 0; u < 16; u++) {
        int j = t + u*256;
        float x = R[j*3]   - rx;
        float y = R[j*3+1] - ry;
        float z = R[j*3+2] - rz;
        float d2 = x*x + y*y + z*z;
        if (j == i) d2 = 1e9f;
        dr[u] = d2;
        int b = (int)fminf(d2 * 0.25f, 255.0f);
        bn[u] = b;
        atomicAdd(&hist[b], 1);
    }
    __syncthreads();

    // parallel cut-bin: warp scans + per-thread warp-prefix, single predicate hit
    {
        int h = hist[t];
        int sc = h;
        #pragma unroll
        for (int off = 1; off < 32; off <<= 1) {
            int o = __shfl_up_sync(0xffffffffu, sc, off);
            if (lane >= off) sc += o;
        }
        if (lane == 31) warpsum[wrp] = sc;
        __syncthreads();
        int wpre = 0;
        #pragma unroll
        for (int w2 = 0; w2 < 8; w2++)
            wpre += (w2 < wrp) ? warpsum[w2] : 0;
        int gcum = wpre + sc;     // inclusive global cumulative at bin t
        if (gcum >= KNN && gcum - h < KNN) s_cutbin = t;
    }
    __syncthreads();

    int cutbin = s_cutbin;
    #pragma unroll
    for (int u = 0; u < 16; u++) {
        if (bn[u] <= cutbin) {
            int p = atomicAdd(&s_cnt, 1);
            if (p < KNN_CAP) { cv[p] = dr[u]; cjj[p] = t + u*256; }
        }
    }
    __syncthreads();
    int cnt = min(s_cnt, KNN_CAP);

    // parallel rank selection: rank = #candidates strictly before (d2, idx)
    for (int p = t; p < cnt; p += 256) {
        float v = cv[p]; int j = cjj[p];
        int rank = 0;
        for (int qq = 0; qq < cnt; qq++) {
            float vq = cv[qq]; int jq = cjj[qq];
            rank += (vq < v || (vq == v && jq < j)) ? 1 : 0;
        }
        if (rank < KNN) sidx[rank] = j;
    }
    __syncthreads();

    if (t < KNN) {
        int j = sidx[t];
        float vx = R[j*3]   - rx;
        float vy = R[j*3+1] - ry;
        float vz = R[j*3+2] - rz;
        float dd = sqrtf(vx*vx + vy*vy + vz*vz + 1e-12f);
        int e = i*KNN + t;
        d_idx[e] = j;
        float c = (dd <= 5.f) ? 0.5f*(cosf(0.62831853071795864769f*dd) + 1.f) : 0.f;
        d_cut[e]  = c;
        d_dist[e] = dd;
    }
}

// ---------------- QKV via m16n8k16 HMMA (fp16 in, fp32 acc, no smem) --------
__global__ __launch_bounds__(128) void qkv_mma(int l) {
    int bm = blockIdx.x, bn = blockIdx.y;
    int wm = threadIdx.x >> 5, lane = threadIdx.x & 31;
    int r0 = bm*64 + wm*16 + (lane >> 2);
    int c0 = (lane & 3)*2;

    unsigned A[8][4];
    #pragma unroll
    for (int kb = 0; kb < 8; kb++) {
        const __half* p0 = d_sh + r0*FDIM + kb*16 + c0;
        const __half* p1 = d_sh + (r0+8)*FDIM + kb*16 + c0;
        A[kb][0] = *(const unsigned*)p0;
        A[kb][1] = *(const unsigned*)p1;
        A[kb][2] = *(const unsigned*)(p0 + 8);
        A[kb][3] = *(const unsigned*)(p1 + 8);
    }

    const uint2* Wp = d_w16 + ((size_t)(l*48 + bn*8) * 8) * 32;

    #pragma unroll
    for (int nb = 0; nb < 8; nb++) {
        float f0 = 0.f, f1 = 0.f, f2 = 0.f, f3 = 0.f;
        #pragma unroll
        for (int kb = 0; kb < 8; kb++) {
            uint2 bv = Wp[(nb*8 + kb)*32 + lane];
            asm volatile(
                "mma.sync.aligned.m16n8k16.row.col.f32.f16.f16.f32 "
                "{%0,%1,%2,%3}, {%4,%5,%6,%7}, {%8,%9}, {%0,%1,%2,%3};"
                : "+f"(f0), "+f"(f1), "+f"(f2), "+f"(f3)
                : "r"(A[kb][0]), "r"(A[kb][1]), "r"(A[kb][2]), "r"(A[kb][3]),
                  "r"(bv.x), "r"(bv.y));
        }
        int ngl = bn*64 + nb*8 + c0;
        if (ngl < 128) {
            *(float2*)&d_q[r0*FDIM + ngl]     = make_float2(f0, f1);
            *(float2*)&d_q[(r0+8)*FDIM + ngl] = make_float2(f2, f3);
        } else if (ngl < 256) {
            int c = ngl - 128;        // k cols c, c+1 -> interleaved slots 2c, 2c+2
            d_kvh[(size_t)r0*256 + 2*c]       = __float2half(f0);
            d_kvh[(size_t)r0*256 + 2*c + 2]   = __float2half(f1);
            d_kvh[(size_t)(r0+8)*256 + 2*c]     = __float2half(f2);
            d_kvh[(size_t)(r0+8)*256 + 2*c + 2] = __float2half(f3);
        } else {
            int c = ngl - 256;        // val cols -> slots 2c+1, 2c+3
            d_kvh[(size_t)r0*256 + 2*c + 1]   = __float2half(f0);
            d_kvh[(size_t)r0*256 + 2*c + 3]   = __float2half(f1);
            d_kvh[(size_t)(r0+8)*256 + 2*c + 1] = __float2half(f2);
            d_kvh[(size_t)(r0+8)*256 + 2*c + 3] = __float2half(f3);
        }
    }
}

// ---------------- fused attention message (reg softmax, paired gathers) -----
__global__ __launch_bounds__(512) void message_kernel(const __half* __restrict__ tabL) {
    __shared__ float scut[4][KNN];
    __shared__ int   si0[4][KNN];
    __shared__ float sfr[4][KNN];
    __shared__ int   sj[4][KNN];

    int sub = threadIdx.x >> 7;
    int f   = threadIdx.x & 127;
    int i   = blockIdx.x*4 + sub;

    if (f < KNN) {
        int e = i*KNN + f;
        sj[sub][f]   = d_idx[e];
        scut[sub][f] = d_cut[e];
        float fi = fminf(d_dist[e] * (4095.0f/5.0f), 4095.0f);
        int i0 = min((int)fi, 4094);
        si0[sub][f] = i0;
        sfr[sub][f] = fi - (float)i0;
    }
    __syncthreads();     // the only block sync

    float q = d_q[i*FDIM + f];
    float prod[KNN], logit[KNN];

    #pragma unroll
    for (int k = 0; k < KNN; k++) {
        int j = sj[sub][k];
        int i0 = si0[sub][k];
        float fr = sfr[sub][k];
        __half2 kv = *(const __half2*)(d_kvh + (size_t)j*256 + 2*f);
        __half2 t0 = *(const __half2*)(tabL + (size_t)i0*ECOL + 2*f);
        __half2 t1 = *(const __half2*)(tabL + (size_t)(i0+1)*ECOL + 2*f);
        float kf = __half2float(__low2half(kv));
        float va = __half2float(__high2half(kv));
        float ek0 = __half2float(__low2half(t0)),  ev0 = __half2float(__high2half(t0));
        float ek1 = __half2float(__low2half(t1)),  ev1 = __half2float(__high2half(t1));
        float ek = fmaf(fr, ek1 - ek0, ek0);
        float ev = fmaf(fr, ev1 - ev0, ev0);
        prod[k] = va * ev;
        float p = q * kf * ek;
        #pragma unroll
        for (int off = 16; off; off >>= 1) p += __shfl_xor_sync(0xffffffffu, p, off);
        logit[k] = p * 0.125f;
    }

    // per-lane redundant softmax over 15 registers (all lanes hold identical logits)
    float mx = logit[0];
    #pragma unroll
    for (int k = 1; k < KNN; k++) mx = fmaxf(mx, logit[k]);
    float sum = 0.f;
    #pragma unroll
    for (int k = 0; k < KNN; k++) { logit[k] = expf(logit[k] - mx); sum += logit[k]; }
    float inv = 1.f / sum;

    float ds = 0.f;
    #pragma unroll
    for (int k = 0; k < KNN; k++)
        ds = fmaf(logit[k] * inv * scut[sub][k], prod[k], ds);

    float sn = d_s[i*FDIM + f] + ds;
    d_s[i*FDIM + f]  = sn;
    d_sh[i*FDIM + f] = __float2half(sn);
    d_o[i*FDIM + f] += ds;
}

// ---------------- layernorm + readout ---------------------------------------
__global__ void readout_kernel(const float* __restrict__ ln_g, const float* __restrict__ ln_b,
                               const float* __restrict__ Wo1,  const float* __restrict__ Wo2) {
    __shared__ float red[128];
    __shared__ float son[128];
    int i = blockIdx.x, f = threadIdx.x;
    float x = d_o[i*FDIM + f];

    red[f] = x; __syncthreads();
    for (int s = 64; s > 0; s >>= 1) { if (f < s) red[f] += red[f+s]; __syncthreads(); }
    float mean = red[0] * (1.f/128.f);
    __syncthreads();

    float dx = x - mean;
    red[f] = dx*dx; __syncthreads();
    for (int s = 64; s > 0; s >>= 1) { if (f < s) red[f] += red[f+s]; __syncthreads(); }
    float var = red[0] * (1.f/128.f);
    __syncthreads();

    float on = dx * (1.f / sqrtf(var + 1e-5f)) * ln_g[f] + ln_b[f];
    son[f] = on; __syncthreads();

    float acc = 0.f;
    #pragma unroll 8
    for (int g = 0; g < 128; g++) acc = fmaf(son[g], Wo1[g*FDIM + f], acc);
    float tb = acc / (1.f + expf(-acc));
    red[f] = tb * Wo2[f];
    __syncthreads();
    for (int s = 64; s > 0; s >>= 1) { if (f < s) red[f] += red[f+s]; __syncthreads(); }
    if (f == 0) d_h[i] = red[0];
}

__global__ void sum_kernel(float* __restrict__ out) {
    __shared__ double rd[256];
    int t = threadIdx.x;
    double a = 0.0;
    for (int i = t; i < NA; i += 256) a += (double)d_h[i];
    rd[t] = a; __syncthreads();
    for (int s = 128; s > 0; s >>= 1) { if (t < s) rd[t] += rd[t+s]; __syncthreads(); }
    if (t == 0) out[0] = (float)rd[0];
}

// ---------------- launch ------------------------------------------------------
extern "C" void kernel_launch(void* const* d_in, const int* in_sizes, int n_in,
                              void* d_out, int out_size) {
    const int*   Z    = (const int*)  d_in[0];
    const float* R    = (const float*)d_in[1];
    const float* emb  = (const float*)d_in[3];
    const float* Wq   = (const float*)d_in[4];
    const float* Wk   = (const float*)d_in[5];
    const float* Wv   = (const float*)d_in[6];
    const float* We_k = (const float*)d_in[7];
    const float* be_k = (const float*)d_in[8];
    const float* We_v = (const float*)d_in[9];
    const float* be_v = (const float*)d_in[10];
    const float* ln_g = (const float*)d_in[11];
    const float* ln_b = (const float*)d_in[12];
    const float* Wo1  = (const float*)d_in[13];
    const float* Wo2  = (const float*)d_in[14];
    float* out = (float*)d_out;

    static __half* tabp = nullptr;
    static cudaStream_t s1 = nullptr;
    static cudaEvent_t evF = nullptr, evI = nullptr, evT = nullptr;
    if (!tabp) {
        cudaGetSymbolAddress((void**)&tabp, d_tab);
        cudaFuncSetAttribute(tablegen_kernel, cudaFuncAttributeMaxDynamicSharedMemorySize, TG_SMEM);
        cudaStreamCreateWithFlags(&s1, cudaStreamNonBlocking);
        cudaEventCreateWithFlags(&evF, cudaEventDisableTiming);
        cudaEventCreateWithFlags(&evI, cudaEventDisableTiming);
        cudaEventCreateWithFlags(&evT, cudaEventDisableTiming);
    }

    // fork s1 (capture-safe): tablegen + wcvt + qkv(0) hidden under knn
    cudaEventRecord(evF, 0);
    cudaStreamWaitEvent(s1, evF, 0);
    tablegen_kernel<<<dim3(TROWS/TG_ROWS, NL), 256, TG_SMEM, s1>>>(We_k, be_k, We_v, be_v);
    wcvt_kernel<<<(NL*48*8*32 + 255)/256, 256, 0, s1>>>(Wq, Wk, Wv);

    // stream0: init (qkv(0) input), then knn
    init_kernel<<<(NA*FDIM + 255)/256, 256>>>(Z, emb);
    cudaEventRecord(evI, 0);
    cudaStreamWaitEvent(s1, evI, 0);
    qkv_mma<<<dim3(NA/64, 6), 128, 0, s1>>>(0);
    cudaEventRecord(evT, s1);

    knn_kernel<<<NA, 256>>>(R);
    cudaStreamWaitEvent(0, evT, 0);   // join: tab + w16 + qkv(0) ready

    for (int l = 0; l < NL; l++) {
        if (l > 0) qkv_mma<<<dim3(NA/64, 6), 128>>>(l);
        message_kernel<<<NA/4, 512>>>(tabp + (size_t)l*TROWS*ECOL);
    }

    readout_kernel<<<NA, 128>>>(ln_g, ln_b, Wo1, Wo2);
    sum_kernel<<<1, 256>>>(out);
}